// round 9
// baseline (speedup 1.0000x reference)
#include <cuda_runtime.h>
#include <cstdint>

#define BS 16
#define A  33600
#define G  64
#define C  80
#define EPSF 1e-7f
#define CAP 4096

#define TILE 256
#define NCHUNK ((A + TILE - 1) / TILE)

#define INV_PI2_4 0.4052847345693511f

// Scratch (device globals — no runtime allocation allowed)
__device__ unsigned long long g_key[(size_t)BS * G * CAP]; // candidate (fkey(cost)<<32 | a)
__device__ int                g_cnt[BS * G];               // candidate counts
__device__ float              g_iov[(size_t)BS * G * CAP]; // positive iouv values per (b,g)
__device__ int                g_icnt[BS * G];              // iou list counts
__device__ float4             g_fpb  [(size_t)BS * A];     // filt anchors: pred box
__device__ float2             g_faux [(size_t)BS * A];     // filt anchors: (w2h2, at2)
__device__ int                g_fa   [(size_t)BS * A];     // filt anchors: anchor index
__device__ unsigned long long g_fmask[(size_t)BS * A];     // filt anchors: ic mask
__device__ int                g_fcnt[BS];                  // filt counts
__device__ unsigned char      g_filt[(size_t)BS * A];      // per-anchor anchor_filter
__device__ unsigned long long g_amin[(size_t)BS * A];      // per-anchor argmin (fkey<<6|g)
__device__ int                g_mcnt[(size_t)BS * A];      // match count per anchor
__device__ int                g_mfg [(size_t)BS * A];      // min matched g per anchor

// Monotone float -> uint32 order-preserving transform
__device__ __forceinline__ unsigned int fkey(float f) {
    unsigned int b = __float_as_uint(f);
    return b ^ ((unsigned int)((int)b >> 31) | 0x80000000u);
}

// ---------------------------------------------------------------------------
// KZ: zero small counters (single block)
// ---------------------------------------------------------------------------
__global__ void kz() {
    int i = threadIdx.x;
    if (i < BS * G) { g_cnt[i] = 0; g_icnt[i] = 0; }
    if (i < BS)     g_fcnt[i] = 0;
}

// ---------------------------------------------------------------------------
// K1a: per (b,a): in-center mask + compaction of filt anchors into per-batch
// lists; also zero-inits per-anchor match state.
// ---------------------------------------------------------------------------
__global__ __launch_bounds__(TILE) void k1a(
    const float* __restrict__ pboxes, const float* __restrict__ anc,
    const float* __restrict__ gbox,   const int*   __restrict__ gmask,
    const float* __restrict__ strd)
{
    __shared__ float2 s_gc[G];
    __shared__ unsigned int s_vm[2];

    const int tid = threadIdx.x;
    const int b   = blockIdx.y;

    if (tid < G) {
        const float* gb = gbox + ((size_t)b * G + tid) * 4;
        s_gc[tid] = make_float2((gb[0] + gb[2]) * 0.5f, (gb[1] + gb[3]) * 0.5f);
        unsigned int bal = __ballot_sync(0xFFFFFFFFu, gmask[b * G + tid] != 0);
        if ((tid & 31) == 0) s_vm[tid >> 5] = bal;
    }
    __syncthreads();

    const int a = blockIdx.x * TILE + tid;
    if (a >= A) return;   // warp-uniform (A % 32 == 0)

    const size_t ba = (size_t)b * A + a;
    g_mcnt[ba] = 0;
    g_mfg [ba] = 0x7FFFFFFF;
    g_amin[ba] = 0xFFFFFFFFFFFFFFFFull;

    const unsigned long long vmask =
        (unsigned long long)s_vm[0] | ((unsigned long long)s_vm[1] << 32);

    const float ax = anc[a * 2 + 0], ay = anc[a * 2 + 1];
    const float cd = strd[ba] * 2.5f;

    unsigned long long mask = 0ull;
    #pragma unroll
    for (int g = 0; g < G; g++) {
        float2 gc = s_gc[g];
        bool ic = (fabsf(ax - gc.x) < cd) && (fabsf(ay - gc.y) < cd);
        mask |= ((unsigned long long)ic) << g;
    }
    mask &= vmask;
    const bool filt = (mask != 0ull);
    g_filt[ba] = filt ? 1 : 0;

    unsigned int fm = __ballot_sync(0xFFFFFFFFu, filt);
    if (filt) {
        const float4 pb = *(const float4*)(pboxes + ba * 4);
        const float w2 = pb.z - pb.x, h2 = pb.w - pb.y;
        int lane   = tid & 31;
        int leader = __ffs(fm) - 1;
        int basei = 0;
        if (lane == leader) basei = atomicAdd(&g_fcnt[b], __popc(fm));
        basei = __shfl_sync(fm, basei, leader);
        int slot = basei + __popc(fm & ((1u << lane) - 1u));
        size_t off = (size_t)b * A + slot;
        g_fpb  [off] = pb;
        g_faux [off] = make_float2(w2 * h2, atanf(__fdividef(w2, h2 + EPSF)));
        g_fa   [off] = a;
        g_fmask[off] = mask;
    }
}

// ---------------------------------------------------------------------------
// K1b: dense pass over the compacted filt-anchor list: 80-class base scan,
// per-gt intersection test; CIoU only when intersecting or in-center.
// Emits: positive iouv values (for dyn_k top-10), cost keys (ic pairs),
// per-anchor argmin.
// ---------------------------------------------------------------------------
__global__ __launch_bounds__(TILE) void k1b(
    const float* __restrict__ scores, const int* __restrict__ glab,
    const float* __restrict__ gbox,   const int* __restrict__ gmask)
{
    __shared__ float4 s_box[G];
    __shared__ float4 s_aux[G];   // sx, sy, w1h1, at1
    __shared__ int    s_lab[G];
    __shared__ unsigned int s_vm[2];

    const int tid = threadIdx.x;
    const int b   = blockIdx.y;

    if (tid < G) {
        const float* gb = gbox + ((size_t)b * G + tid) * 4;
        float x1 = gb[0], y1 = gb[1], x2 = gb[2], y2 = gb[3];
        s_box[tid] = make_float4(x1, y1, x2, y2);
        float w1 = x2 - x1, h1 = y2 - y1;
        s_aux[tid] = make_float4(x1 + x2, y1 + y2, w1 * h1, atanf(__fdividef(w1, h1 + EPSF)));
        s_lab[tid] = glab[b * G + tid];
        unsigned int bal = __ballot_sync(0xFFFFFFFFu, gmask[b * G + tid] != 0);
        if ((tid & 31) == 0) s_vm[tid >> 5] = bal;
    }
    __syncthreads();

    const int i = blockIdx.x * TILE + tid;
    if (i >= g_fcnt[b]) return;

    const size_t off = (size_t)b * A + i;
    const int a = g_fa[off];
    const float4 pb = g_fpb[off];
    const float2 au2 = g_faux[off];
    const float w2h2 = au2.x, at2 = au2.y;
    const unsigned long long mask = g_fmask[off];
    const float psx = pb.x + pb.z, psy = pb.y + pb.w;
    const unsigned long long vmask =
        (unsigned long long)s_vm[0] | ((unsigned long long)s_vm[1] << 32);

    const size_t ba = (size_t)b * A + a;
    const float* srow = scores + ba * C;

    // base = sum_c -log1p(-sqrt(s_c))
    float base = 0.0f;
    const float4* srow4 = (const float4*)srow;
    #pragma unroll
    for (int q = 0; q < C / 4; q++) {
        float4 v = srow4[q];
        float ss[4] = {v.x, v.y, v.z, v.w};
        #pragma unroll
        for (int j = 0; j < 4; j++) {
            float p = __fsqrt_rn(ss[j]);
            base -= fmaxf(__logf(1.0f - p), -100.0f);
        }
    }

    unsigned long long amin = 0xFFFFFFFFFFFFFFFFull;
    #pragma unroll 4
    for (int g = 0; g < G; g++) {
        if (!((vmask >> g) & 1ull)) continue;   // warp-uniform skip
        const float4 bx = s_box[g];
        const float4 au = s_aux[g];
        float iw = fmaxf(fminf(bx.z, pb.z) - fmaxf(bx.x, pb.x), 0.0f);
        float ih = fmaxf(fminf(bx.w, pb.w) - fmaxf(bx.y, pb.y), 0.0f);
        float inter = iw * ih;
        const bool ic = (mask >> g) & 1ull;
        if (inter > 0.0f || ic) {
            float uni   = au.z + w2h2 - inter + EPSF;
            float iou   = __fdividef(inter, uni);
            float cw    = fmaxf(bx.z, pb.z) - fminf(bx.x, pb.x);
            float ch    = fmaxf(bx.w, pb.w) - fminf(bx.y, pb.y);
            float c2    = cw * cw + ch * ch + EPSF;
            float dx    = psx - au.x, dy = psy - au.y;
            float rho2  = (dx * dx + dy * dy) * 0.25f;
            float da    = at2 - au.w;
            float v     = INV_PI2_4 * da * da;
            float alpha = __fdividef(v, v - iou + (1.0f + EPSF));
            float ciou  = iou - (__fdividef(rho2, c2) + v * alpha);
            float iouv  = fmaxf(ciou, 0.0f);

            if (iouv > 0.0f) {   // zeros never affect top-10 (init 0)
                int slot = atomicAdd(&g_icnt[b * G + g], 1);
                if (slot < CAP) g_iov[(size_t)(b * G + g) * CAP + slot] = iouv;
            }
            if (ic) {
                float s   = srow[s_lab[g]];
                float p   = __fsqrt_rn(s);
                float lp  = fmaxf(0.5f * __logf(s), -100.0f);
                float l1m = fmaxf(__logf(1.0f - p), -100.0f);
                float cost = base + (l1m - lp) - 3.0f * __logf(iouv + 1e-8f);

                unsigned int k32 = fkey(cost);
                unsigned long long pk = (((unsigned long long)k32) << 6) | (unsigned int)g;
                if (pk < amin) amin = pk;

                int slot = atomicAdd(&g_cnt[b * G + g], 1);
                if (slot < CAP)
                    g_key[(size_t)(b * G + g) * CAP + slot] =
                        (((unsigned long long)k32) << 32) | (unsigned int)a;
            }
        }
    }
    g_amin[ba] = amin;
}

// ---------------------------------------------------------------------------
// K2: ONE WARP per (b,g), no __syncthreads.
// Phase A: top-10 over precomputed iouv list -> dyn_k (sum in descending
// order, matching top_k sum order). Phase B: dyn_k-th smallest cost key -> T;
// mark matches.
// ---------------------------------------------------------------------------
__global__ __launch_bounds__(256) void k2(
    const float* __restrict__ scores, const float* __restrict__ pboxes,
    const int* __restrict__ glab, const float* __restrict__ gbox,
    const int* __restrict__ gmask)
{
    const int tid  = threadIdx.x;
    const int lane = tid & 31;
    const int bg   = blockIdx.x * 8 + (tid >> 5);
    const int b = bg >> 6, g = bg & 63;
    if (gmask[bg] == 0) return;   // warp-uniform

    // ---- Phase A: dyn_k via warp top-10 extraction ----
    const int n_i = min(g_icnt[bg], CAP);
    const float* iol = g_iov + (size_t)bg * CAP;
    float top[10];
    #pragma unroll
    for (int j = 0; j < 10; j++) top[j] = 0.0f;
    for (int i = lane; i < n_i; i += 32) {
        float v = iol[i];
        if (v > top[9]) {
            top[9] = v;
            #pragma unroll
            for (int j = 8; j >= 0; j--)
                if (top[j + 1] > top[j]) { float t = top[j]; top[j] = top[j + 1]; top[j + 1] = t; }
        }
    }
    float sum = 0.0f;
    int p = 0;
    #pragma unroll
    for (int r = 0; r < 10; r++) {
        float cand = (p < 10) ? top[p] : 0.0f;
        unsigned long long key =
            (((unsigned long long)__float_as_uint(cand)) << 6) | (unsigned int)lane;
        #pragma unroll
        for (int o = 16; o > 0; o >>= 1) {
            unsigned long long ok = __shfl_xor_sync(0xFFFFFFFFu, key, o);
            if (ok > key) key = ok;
        }
        sum += __uint_as_float((unsigned int)(key >> 6));   // identical on all lanes
        if ((int)(key & 63ull) == lane && p < 10) p++;
    }
    const int dynk = max((int)(sum + 0.5f), 1);

    // ---- Phase B: dyn_k-th smallest candidate key -> T; mark matches ----
    const int n = min(g_cnt[bg], CAP);
    const unsigned long long* kl = g_key + (size_t)bg * CAP;

    if (n > 0) {
        unsigned long long bot[10];
        #pragma unroll
        for (int j = 0; j < 10; j++) bot[j] = 0xFFFFFFFFFFFFFFFFull;
        for (int i = lane; i < n; i += 32) {
            unsigned long long key = kl[i];
            if (key < bot[9]) {
                bot[9] = key;
                #pragma unroll
                for (int j = 8; j >= 0; j--)
                    if (bot[j + 1] < bot[j]) { unsigned long long t = bot[j]; bot[j] = bot[j + 1]; bot[j + 1] = t; }
            }
        }
        int q = 0;
        unsigned long long T = 0xFFFFFFFFFFFFFFFFull;
        for (int r = 0; r < dynk; r++) {
            unsigned long long cand = (q < 10) ? bot[q] : 0xFFFFFFFFFFFFFFFFull;
            unsigned long long m = cand;
            #pragma unroll
            for (int o = 16; o > 0; o >>= 1) {
                unsigned long long om = __shfl_xor_sync(0xFFFFFFFFu, m, o);
                if (om < m) m = om;
            }
            T = m;
            if (cand == m && q < 10) q++;   // unique keys (contain anchor id)
        }
        for (int i = lane; i < n; i += 32) {
            unsigned long long key = kl[i];
            if (key <= T) {
                unsigned int aa = (unsigned int)key;
                atomicAdd(&g_mcnt[(size_t)b * A + aa], 1);
                atomicMin(&g_mfg [(size_t)b * A + aa], g);
            }
        }
    } else {
        // Fallback (statistically unreachable): warp-level global row min.
        const float* gb = gbox + (size_t)bg * 4;
        const float x1 = gb[0], y1 = gb[1], x2 = gb[2], y2 = gb[3];
        const float w1 = x2 - x1, h1 = y2 - y1, w1h1 = w1 * h1;
        const float at1 = atanf(__fdividef(w1, h1 + EPSF));
        const float sx = x1 + x2, sy = y1 + y2;
        const int lab = glab[bg];
        unsigned long long best = 0xFFFFFFFFFFFFFFFFull;
        for (int a = lane; a < A; a += 32) {
            const size_t ba = (size_t)b * A + a;
            float4 pb = *(const float4*)(pboxes + ba * 4);
            float w2 = pb.z - pb.x, h2 = pb.w - pb.y;
            float iw = fmaxf(fminf(x2, pb.z) - fmaxf(x1, pb.x), 0.0f);
            float ih = fmaxf(fminf(y2, pb.w) - fmaxf(y1, pb.y), 0.0f);
            float inter = iw * ih;
            float uni   = w1h1 + w2 * h2 - inter + EPSF;
            float iou   = __fdividef(inter, uni);
            float cw    = fmaxf(x2, pb.z) - fminf(x1, pb.x);
            float ch    = fmaxf(y2, pb.w) - fminf(y1, pb.y);
            float c2    = cw * cw + ch * ch + EPSF;
            float dx    = (pb.x + pb.z) - sx, dy = (pb.y + pb.w) - sy;
            float rho2  = (dx * dx + dy * dy) * 0.25f;
            float at2   = atanf(__fdividef(w2, h2 + EPSF));
            float da    = at2 - at1;
            float v     = INV_PI2_4 * da * da;
            float alpha = __fdividef(v, v - iou + (1.0f + EPSF));
            float ciou  = iou - (__fdividef(rho2, c2) + v * alpha);

            bool filt = g_filt[ba] != 0;
            float iouv = filt ? fmaxf(ciou, 0.0f) : 0.0f;

            float base = 0.0f;
            const float4* s4 = (const float4*)(scores + ba * C);
            #pragma unroll 4
            for (int qq = 0; qq < C / 4; qq++) {
                float4 vv = s4[qq];
                base -= fmaxf(__logf(1.0f - __fsqrt_rn(vv.x)), -100.0f);
                base -= fmaxf(__logf(1.0f - __fsqrt_rn(vv.y)), -100.0f);
                base -= fmaxf(__logf(1.0f - __fsqrt_rn(vv.z)), -100.0f);
                base -= fmaxf(__logf(1.0f - __fsqrt_rn(vv.w)), -100.0f);
            }
            float s = scores[ba * C + lab];
            float pp = __fsqrt_rn(s);
            float lp  = fmaxf(0.5f * __logf(s), -100.0f);
            float l1m = fmaxf(__logf(1.0f - pp), -100.0f);
            float cost = base + (l1m - lp) - 3.0f * __logf(iouv + 1e-8f)
                       + 1e6f + (filt ? 0.0f : 1e8f);
            unsigned long long key = (((unsigned long long)fkey(cost)) << 32) | (unsigned int)a;
            if (key < best) best = key;
        }
        #pragma unroll
        for (int o = 16; o > 0; o >>= 1) {
            unsigned long long om = __shfl_xor_sync(0xFFFFFFFFu, best, o);
            if (om < best) best = om;
        }
        if (lane == 0) {
            unsigned int aa = (unsigned int)best;
            atomicAdd(&g_mcnt[(size_t)b * A + aa], 1);
            atomicMin(&g_mfg [(size_t)b * A + aa], g);
            atomicMin(&g_amin[(size_t)b * A + aa],
                      ((best >> 32) << 6) | (unsigned long long)g);
        }
    }
}

// ---------------------------------------------------------------------------
// K3: per anchor: resolve matches, recompute pred_iou, coalesced outputs.
// Output layout (tuple order): labels | tboxes | tscores | fg | tgt_idx
// ---------------------------------------------------------------------------
__global__ __launch_bounds__(TILE) void k3(
    const float* __restrict__ pboxes, const int* __restrict__ glab,
    const float* __restrict__ gbox,   const int* __restrict__ gmask,
    float* __restrict__ out)
{
    __shared__ float4 s_box[G];
    __shared__ float4 s_aux[G];   // sx, sy, w1h1, at1
    __shared__ int    s_lab[G], s_val[G];
    __shared__ int    r_mg[TILE];
    __shared__ float  r_m [TILE];

    const int tid = threadIdx.x;
    const int b   = blockIdx.y;
    if (tid < G) {
        const float* gb = gbox + ((size_t)b * G + tid) * 4;
        float x1 = gb[0], y1 = gb[1], x2 = gb[2], y2 = gb[3];
        s_box[tid] = make_float4(x1, y1, x2, y2);
        float w1 = x2 - x1, h1 = y2 - y1;
        s_aux[tid] = make_float4(x1 + x2, y1 + y2, w1 * h1, atanf(__fdividef(w1, h1 + EPSF)));
        s_lab[tid] = glab[b * G + tid];
        s_val[tid] = gmask[b * G + tid];
    }
    __syncthreads();

    const int blockbase = blockIdx.x * TILE;
    const int count = min(TILE, A - blockbase);
    const int a = blockbase + tid;

    float piou = 0.0f;
    int   lab  = 0;
    if (tid < count) {
        const size_t ba = (size_t)b * A + a;
        const int cnt = g_mcnt[ba];
        const bool fg = (cnt > 0);
        int mg = 0;
        if (fg) {
            mg = (cnt > 1) ? (int)(g_amin[ba] & 63ull) : g_mfg[ba];
            float4 pb = *(const float4*)(pboxes + ba * 4);
            float4 bx = s_box[mg];
            float4 au = s_aux[mg];
            float w2 = pb.z - pb.x, h2 = pb.w - pb.y;
            float iw = fmaxf(fminf(bx.z, pb.z) - fmaxf(bx.x, pb.x), 0.0f);
            float ih = fmaxf(fminf(bx.w, pb.w) - fmaxf(bx.y, pb.y), 0.0f);
            float inter = iw * ih;
            float uni   = au.z + w2 * h2 - inter + EPSF;
            float iou   = __fdividef(inter, uni);
            float cw    = fmaxf(bx.z, pb.z) - fminf(bx.x, pb.x);
            float ch    = fmaxf(bx.w, pb.w) - fminf(bx.y, pb.y);
            float c2    = cw * cw + ch * ch + EPSF;
            float dx    = (pb.x + pb.z) - au.x, dy = (pb.y + pb.w) - au.y;
            float rho2  = (dx * dx + dy * dy) * 0.25f;
            float at2   = atanf(__fdividef(w2, h2 + EPSF));
            float da    = at2 - au.w;
            float v     = INV_PI2_4 * da * da;
            float alpha = __fdividef(v, v - iou + (1.0f + EPSF));
            float ciou  = iou - (__fdividef(rho2, c2) + v * alpha);
            bool filt = (g_filt[ba] != 0);
            piou = (filt && (s_val[mg] != 0)) ? fmaxf(ciou, 0.0f) : 0.0f;
        }
        lab        = s_lab[mg];
        r_mg[tid]  = fg ? mg : 0;
        r_m[tid]   = fg ? 1.0f : 0.0f;
    }
    __syncthreads();

    const size_t N  = (size_t)BS * A;
    const size_t bb = (size_t)b * A + blockbase;
    float4* os = (float4*)(out + N * 5 + bb * 80);
    const float4 z4 = make_float4(0.f, 0.f, 0.f, 0.f);

    if (count == TILE) {
        const float m = r_m[tid];
        out[bb + tid]          = (m != 0.0f) ? (float)lab : (float)C;
        out[N * 85 + bb + tid] = m;
        out[N * 86 + bb + tid] = (float)r_mg[tid];
        #pragma unroll
        for (int k = 0; k < 4; k++) {
            int i = k * TILE + tid;
            int al = i >> 2, cp = i & 3;
            out[N + bb * 4 + i] = ((const float*)s_box)[r_mg[al] * 4 + cp] * r_m[al];
        }
        #pragma unroll
        for (int k = 0; k < 20; k++) os[k * TILE + tid] = z4;
        __syncthreads();
        if (r_m[tid] != 0.0f)
            out[N * 5 + (bb + tid) * 80 + lab] = piou;
    } else {
        if (tid < count) {
            const float m = r_m[tid];
            out[bb + tid]          = (m != 0.0f) ? (float)lab : (float)C;
            out[N * 85 + bb + tid] = m;
            out[N * 86 + bb + tid] = (float)r_mg[tid];
        }
        for (int i = tid; i < count * 4; i += TILE) {
            int al = i >> 2, cp = i & 3;
            out[N + bb * 4 + i] = ((const float*)s_box)[r_mg[al] * 4 + cp] * r_m[al];
        }
        for (int i = tid; i < count * 20; i += TILE) os[i] = z4;
        __syncthreads();
        if (tid < count && r_m[tid] != 0.0f)
            out[N * 5 + (bb + tid) * 80 + lab] = piou;
    }
}

// ---------------------------------------------------------------------------
extern "C" void kernel_launch(void* const* d_in, const int* in_sizes, int n_in,
                              void* d_out, int out_size)
{
    const float* scores = (const float*)d_in[0];   // (16, 33600, 80)
    const float* pboxes = (const float*)d_in[1];   // (16, 33600, 4)
    const float* anc    = (const float*)d_in[2];   // (33600, 2)
    const int*   glab   = (const int*)  d_in[3];   // (16, 64, 1)
    const float* gbox   = (const float*)d_in[4];   // (16, 64, 4)
    const int*   gmask  = (const int*)  d_in[5];   // (16, 64, 1)
    const float* strd   = (const float*)d_in[6];   // (16, 33600, 1)
    float* out = (float*)d_out;

    kz<<<1, 1024>>>();
    dim3 gg(NCHUNK, BS);
    k1a<<<gg, TILE>>>(pboxes, anc, gbox, gmask, strd);
    k1b<<<gg, TILE>>>(scores, glab, gbox, gmask);
    k2<<<BS * G / 8, 256>>>(scores, pboxes, glab, gbox, gmask);
    k3<<<gg, TILE>>>(pboxes, glab, gbox, gmask, out);
}

// round 10
// speedup vs baseline: 1.3610x; 1.3610x over previous
#include <cuda_runtime.h>
#include <cstdint>

#define BS 16
#define A  33600
#define G  64
#define C  80
#define EPSF 1e-7f
#define CAP 4096

#define TILE 256
#define NCHUNK ((A + TILE - 1) / TILE)

#define INV_PI2_4 0.4052847345693511f

// Scratch (device globals — no runtime allocation allowed)
__device__ unsigned long long g_key[(size_t)BS * G * CAP]; // candidate (fkey(cost)<<32 | a)
__device__ int                g_cnt[BS * G];               // candidate counts
__device__ float4             g_fpb  [(size_t)BS * A];     // filt anchors: pred box
__device__ int                g_fa   [(size_t)BS * A];     // filt anchors: anchor index
__device__ unsigned long long g_fmask[(size_t)BS * A];     // filt anchors: ic mask
__device__ int                g_fcnt[BS];                  // filt counts
__device__ unsigned char      g_filt[(size_t)BS * A];      // per-anchor anchor_filter
__device__ unsigned long long g_amin[(size_t)BS * A];      // per-anchor argmin (fkey<<6|g)
__device__ int                g_mcnt[(size_t)BS * A];      // match count per anchor
__device__ int                g_mfg [(size_t)BS * A];      // min matched g per anchor

// Monotone float -> uint32 order-preserving transform
__device__ __forceinline__ unsigned int fkey(float f) {
    unsigned int b = __float_as_uint(f);
    return b ^ ((unsigned int)((int)b >> 31) | 0x80000000u);
}

// ---------------------------------------------------------------------------
// KZ: zero small counters (single block)
// ---------------------------------------------------------------------------
__global__ void kz() {
    int i = threadIdx.x;
    if (i < BS * G) g_cnt[i] = 0;
    if (i < BS)     g_fcnt[i] = 0;
}

// ---------------------------------------------------------------------------
// K1a: per (b,a): in-center mask + compaction of filt anchors into per-batch
// lists; also zero-inits per-anchor match state.
// ---------------------------------------------------------------------------
__global__ __launch_bounds__(TILE) void k1a(
    const float* __restrict__ pboxes, const float* __restrict__ anc,
    const float* __restrict__ gbox,   const int*   __restrict__ gmask,
    const float* __restrict__ strd)
{
    __shared__ float2 s_gc[G];
    __shared__ unsigned int s_vm[2];

    const int tid = threadIdx.x;
    const int b   = blockIdx.y;

    if (tid < G) {
        const float* gb = gbox + ((size_t)b * G + tid) * 4;
        s_gc[tid] = make_float2((gb[0] + gb[2]) * 0.5f, (gb[1] + gb[3]) * 0.5f);
        unsigned int bal = __ballot_sync(0xFFFFFFFFu, gmask[b * G + tid] != 0);
        if ((tid & 31) == 0) s_vm[tid >> 5] = bal;
    }
    __syncthreads();

    const int a = blockIdx.x * TILE + tid;
    if (a >= A) return;   // warp-uniform (A % 32 == 0)

    const size_t ba = (size_t)b * A + a;
    g_mcnt[ba] = 0;
    g_mfg [ba] = 0x7FFFFFFF;
    g_amin[ba] = 0xFFFFFFFFFFFFFFFFull;

    const unsigned long long vmask =
        (unsigned long long)s_vm[0] | ((unsigned long long)s_vm[1] << 32);

    const float ax = anc[a * 2 + 0], ay = anc[a * 2 + 1];
    const float cd = strd[ba] * 2.5f;

    unsigned long long mask = 0ull;
    #pragma unroll
    for (int g = 0; g < G; g++) {
        float2 gc = s_gc[g];
        bool ic = (fabsf(ax - gc.x) < cd) && (fabsf(ay - gc.y) < cd);
        mask |= ((unsigned long long)ic) << g;
    }
    mask &= vmask;
    const bool filt = (mask != 0ull);
    g_filt[ba] = filt ? 1 : 0;

    unsigned int fm = __ballot_sync(0xFFFFFFFFu, filt);
    if (filt) {
        const float4 pb = *(const float4*)(pboxes + ba * 4);
        int lane   = tid & 31;
        int leader = __ffs(fm) - 1;
        int basei = 0;
        if (lane == leader) basei = atomicAdd(&g_fcnt[b], __popc(fm));
        basei = __shfl_sync(fm, basei, leader);
        int slot = basei + __popc(fm & ((1u << lane) - 1u));
        size_t off = (size_t)b * A + slot;
        g_fpb  [off] = pb;
        g_fa   [off] = a;
        g_fmask[off] = mask;
    }
}

// ---------------------------------------------------------------------------
// K1b: dense pass over the compacted filt-anchor list: 80-class base scan,
// sparse CIoU+cost for in-center gts, candidate emission, per-anchor argmin.
// ---------------------------------------------------------------------------
__global__ __launch_bounds__(TILE) void k1b(
    const float* __restrict__ scores, const int* __restrict__ glab,
    const float* __restrict__ gbox)
{
    __shared__ float4 s_box[G];
    __shared__ float4 s_aux[G];   // sx, sy, w1h1, at1
    __shared__ int    s_lab[G];

    const int tid = threadIdx.x;
    const int b   = blockIdx.y;

    if (tid < G) {
        const float* gb = gbox + ((size_t)b * G + tid) * 4;
        float x1 = gb[0], y1 = gb[1], x2 = gb[2], y2 = gb[3];
        s_box[tid] = make_float4(x1, y1, x2, y2);
        float w1 = x2 - x1, h1 = y2 - y1;
        s_aux[tid] = make_float4(x1 + x2, y1 + y2, w1 * h1, atanf(__fdividef(w1, h1 + EPSF)));
        s_lab[tid] = glab[b * G + tid];
    }
    __syncthreads();

    const int i = blockIdx.x * TILE + tid;
    if (i >= g_fcnt[b]) return;

    const size_t off = (size_t)b * A + i;
    const int a = g_fa[off];
    const float4 pb = g_fpb[off];
    const float w2 = pb.z - pb.x, h2 = pb.w - pb.y;
    const float w2h2 = w2 * h2;
    const float at2  = atanf(__fdividef(w2, h2 + EPSF));
    unsigned long long mm = g_fmask[off];
    const float psx = pb.x + pb.z, psy = pb.y + pb.w;

    const size_t ba = (size_t)b * A + a;
    const float* srow = scores + ba * C;

    // base = sum_c -log1p(-sqrt(s_c))
    float base = 0.0f;
    const float4* srow4 = (const float4*)srow;
    #pragma unroll
    for (int q = 0; q < C / 4; q++) {
        float4 v = srow4[q];
        float ss[4] = {v.x, v.y, v.z, v.w};
        #pragma unroll
        for (int j = 0; j < 4; j++) {
            float p = __fsqrt_rn(ss[j]);
            base -= fmaxf(__logf(1.0f - p), -100.0f);
        }
    }

    unsigned long long amin = 0xFFFFFFFFFFFFFFFFull;
    while (mm) {
        int g = __ffsll((long long)mm) - 1;
        mm &= mm - 1;
        const float4 bx = s_box[g];
        const float4 au = s_aux[g];
        float iw = fmaxf(fminf(bx.z, pb.z) - fmaxf(bx.x, pb.x), 0.0f);
        float ih = fmaxf(fminf(bx.w, pb.w) - fmaxf(bx.y, pb.y), 0.0f);
        float inter = iw * ih;
        float uni   = au.z + w2h2 - inter + EPSF;
        float iou   = __fdividef(inter, uni);
        float cw    = fmaxf(bx.z, pb.z) - fminf(bx.x, pb.x);
        float ch    = fmaxf(bx.w, pb.w) - fminf(bx.y, pb.y);
        float c2    = cw * cw + ch * ch + EPSF;
        float dx    = psx - au.x, dy = psy - au.y;
        float rho2  = (dx * dx + dy * dy) * 0.25f;
        float da    = at2 - au.w;
        float v     = INV_PI2_4 * da * da;
        float alpha = __fdividef(v, v - iou + (1.0f + EPSF));
        float ciou  = iou - (__fdividef(rho2, c2) + v * alpha);
        float iouv  = fmaxf(ciou, 0.0f);

        float s   = srow[s_lab[g]];
        float p   = __fsqrt_rn(s);
        float lp  = fmaxf(0.5f * __logf(s), -100.0f);
        float l1m = fmaxf(__logf(1.0f - p), -100.0f);

        float cost = base + (l1m - lp) - 3.0f * __logf(iouv + 1e-8f);

        unsigned int k32 = fkey(cost);
        unsigned long long pk = (((unsigned long long)k32) << 6) | (unsigned int)g;
        if (pk < amin) amin = pk;

        int slot = atomicAdd(&g_cnt[b * G + g], 1);
        if (slot < CAP)
            g_key[(size_t)(b * G + g) * CAP + slot] =
                (((unsigned long long)k32) << 32) | (unsigned int)a;
    }
    g_amin[ba] = amin;
}

// ---------------------------------------------------------------------------
// K2: block per (b,g). Phase A: pruned scan over filt anchors -> per-thread
// top-10 -> per-warp packed-shuffle top-10 (no barriers) -> warp 0 merge ->
// dyn_k. Phase B (warp 0 only): dyn_k-th smallest cost key -> T; mark.
// Pruning exact: iouv <= iou, and iou > t  <=>  inter > t*uni.
// ---------------------------------------------------------------------------
__global__ __launch_bounds__(256) void k2(
    const float* __restrict__ scores, const float* __restrict__ pboxes,
    const int* __restrict__ glab, const float* __restrict__ gbox,
    const int* __restrict__ gmask)
{
    __shared__ float s_w[80];   // 8 warps x top-10

    const int bg  = blockIdx.x;
    const int tid = threadIdx.x;
    const int lane = tid & 31, wid = tid >> 5;
    const int b = bg >> 6, g = bg & 63;
    if (gmask[bg] == 0) return;

    const float* gb = gbox + (size_t)bg * 4;
    const float x1 = gb[0], y1 = gb[1], x2 = gb[2], y2 = gb[3];
    const float w1 = x2 - x1, h1 = y2 - y1, w1h1 = w1 * h1;
    const float at1 = atanf(__fdividef(w1, h1 + EPSF));
    const float sx = x1 + x2, sy = y1 + y2;

    // ---- Phase A: pruned scan, per-thread top-10 ----
    const int n_f = g_fcnt[b];
    float top[10];
    #pragma unroll
    for (int j = 0; j < 10; j++) top[j] = 0.0f;   // iouv >= 0; zero-padding exact

    for (int i = tid; i < n_f; i += 256) {
        float4 pb = g_fpb[(size_t)b * A + i];
        float w2 = pb.z - pb.x, h2 = pb.w - pb.y;
        float iw = fmaxf(fminf(x2, pb.z) - fmaxf(x1, pb.x), 0.0f);
        float ih = fmaxf(fminf(y2, pb.w) - fmaxf(y1, pb.y), 0.0f);
        float inter = iw * ih;
        float uni   = w1h1 + w2 * h2 - inter + EPSF;
        if (inter > top[9] * uni) {       // exact: iou > top[9]; implies inter > 0
            float iou   = __fdividef(inter, uni);
            float cw    = fmaxf(x2, pb.z) - fminf(x1, pb.x);
            float ch    = fmaxf(y2, pb.w) - fminf(y1, pb.y);
            float c2    = cw * cw + ch * ch + EPSF;
            float dx    = (pb.x + pb.z) - sx, dy = (pb.y + pb.w) - sy;
            float rho2  = (dx * dx + dy * dy) * 0.25f;
            float at2   = atanf(__fdividef(w2, h2 + EPSF));
            float da    = at2 - at1;
            float v     = INV_PI2_4 * da * da;
            float alpha = __fdividef(v, v - iou + (1.0f + EPSF));
            float ciou  = iou - (__fdividef(rho2, c2) + v * alpha);
            float iouv  = fmaxf(ciou, 0.0f);
            if (iouv > top[9]) {
                top[9] = iouv;
                #pragma unroll
                for (int j = 8; j >= 0; j--)
                    if (top[j + 1] > top[j]) { float t = top[j]; top[j] = top[j + 1]; top[j + 1] = t; }
            }
        }
    }

    // ---- Per-warp packed-shuffle top-10 extraction (values >= 0) ----
    {
        int p = 0;
        #pragma unroll
        for (int r = 0; r < 10; r++) {
            float cand = (p < 10) ? top[p] : 0.0f;
            unsigned long long key =
                (((unsigned long long)__float_as_uint(cand)) << 6) | (unsigned int)lane;
            #pragma unroll
            for (int o = 16; o > 0; o >>= 1) {
                unsigned long long ok = __shfl_xor_sync(0xFFFFFFFFu, key, o);
                if (ok > key) key = ok;
            }
            if (lane == 0) s_w[wid * 10 + r] = __uint_as_float((unsigned int)(key >> 6));
            if ((int)(key & 63ull) == lane && p < 10) p++;
        }
    }
    __syncthreads();

    if (wid != 0) return;

    // ---- Warp 0: merge 80 warp-top values -> global top-10 -> dyn_k ----
    float loc[3];
    loc[0] = loc[1] = loc[2] = 0.0f;
    #pragma unroll
    for (int k = 0; k < 3; k++) {
        int idx = lane + 32 * k;
        float v = (idx < 80) ? s_w[idx] : 0.0f;
        if (v > loc[2]) {
            loc[2] = v;
            if (loc[2] > loc[1]) { float t = loc[1]; loc[1] = loc[2]; loc[2] = t; }
            if (loc[1] > loc[0]) { float t = loc[0]; loc[0] = loc[1]; loc[1] = t; }
        }
    }
    float sum = 0.0f;
    {
        int p = 0;
        #pragma unroll
        for (int r = 0; r < 10; r++) {
            float cand = (p < 3) ? loc[p] : 0.0f;
            unsigned long long key =
                (((unsigned long long)__float_as_uint(cand)) << 6) | (unsigned int)lane;
            #pragma unroll
            for (int o = 16; o > 0; o >>= 1) {
                unsigned long long ok = __shfl_xor_sync(0xFFFFFFFFu, key, o);
                if (ok > key) key = ok;
            }
            sum += __uint_as_float((unsigned int)(key >> 6));
            if ((int)(key & 63ull) == lane && p < 3) p++;
        }
    }
    const int dynk = max((int)(sum + 0.5f), 1);

    // ---- Phase B (warp 0): dyn_k-th smallest candidate key -> T; mark ----
    const int n = min(g_cnt[bg], CAP);
    const unsigned long long* kl = g_key + (size_t)bg * CAP;

    if (n > 0) {
        unsigned long long bot[10];
        #pragma unroll
        for (int j = 0; j < 10; j++) bot[j] = 0xFFFFFFFFFFFFFFFFull;
        for (int i = lane; i < n; i += 32) {
            unsigned long long key = kl[i];
            if (key < bot[9]) {
                bot[9] = key;
                #pragma unroll
                for (int j = 8; j >= 0; j--)
                    if (bot[j + 1] < bot[j]) { unsigned long long t = bot[j]; bot[j] = bot[j + 1]; bot[j + 1] = t; }
            }
        }
        int q = 0;
        unsigned long long T = 0xFFFFFFFFFFFFFFFFull;
        for (int r = 0; r < dynk; r++) {
            unsigned long long cand = (q < 10) ? bot[q] : 0xFFFFFFFFFFFFFFFFull;
            unsigned long long m = cand;
            #pragma unroll
            for (int o = 16; o > 0; o >>= 1) {
                unsigned long long om = __shfl_xor_sync(0xFFFFFFFFu, m, o);
                if (om < m) m = om;
            }
            T = m;
            if (cand == m && q < 10) q++;   // keys unique (contain anchor id)
        }
        for (int i = lane; i < n; i += 32) {
            unsigned long long key = kl[i];
            if (key <= T) {
                unsigned int aa = (unsigned int)key;
                atomicAdd(&g_mcnt[(size_t)b * A + aa], 1);
                atomicMin(&g_mfg [(size_t)b * A + aa], g);
            }
        }
    } else {
        // Fallback (statistically unreachable): warp-level global row min.
        const int lab = glab[bg];
        unsigned long long best = 0xFFFFFFFFFFFFFFFFull;
        for (int a = lane; a < A; a += 32) {
            const size_t ba = (size_t)b * A + a;
            float4 pb = *(const float4*)(pboxes + ba * 4);
            float w2 = pb.z - pb.x, h2 = pb.w - pb.y;
            float iw = fmaxf(fminf(x2, pb.z) - fmaxf(x1, pb.x), 0.0f);
            float ih = fmaxf(fminf(y2, pb.w) - fmaxf(y1, pb.y), 0.0f);
            float inter = iw * ih;
            float uni   = w1h1 + w2 * h2 - inter + EPSF;
            float iou   = __fdividef(inter, uni);
            float cw    = fmaxf(x2, pb.z) - fminf(x1, pb.x);
            float ch    = fmaxf(y2, pb.w) - fminf(y1, pb.y);
            float c2    = cw * cw + ch * ch + EPSF;
            float dx    = (pb.x + pb.z) - sx, dy = (pb.y + pb.w) - sy;
            float rho2  = (dx * dx + dy * dy) * 0.25f;
            float at2   = atanf(__fdividef(w2, h2 + EPSF));
            float da    = at2 - at1;
            float v     = INV_PI2_4 * da * da;
            float alpha = __fdividef(v, v - iou + (1.0f + EPSF));
            float ciou  = iou - (__fdividef(rho2, c2) + v * alpha);

            bool filt = g_filt[ba] != 0;
            float iouv = filt ? fmaxf(ciou, 0.0f) : 0.0f;

            float base = 0.0f;
            const float4* s4 = (const float4*)(scores + ba * C);
            #pragma unroll 4
            for (int qq = 0; qq < C / 4; qq++) {
                float4 vv = s4[qq];
                base -= fmaxf(__logf(1.0f - __fsqrt_rn(vv.x)), -100.0f);
                base -= fmaxf(__logf(1.0f - __fsqrt_rn(vv.y)), -100.0f);
                base -= fmaxf(__logf(1.0f - __fsqrt_rn(vv.z)), -100.0f);
                base -= fmaxf(__logf(1.0f - __fsqrt_rn(vv.w)), -100.0f);
            }
            float s = scores[ba * C + lab];
            float pp = __fsqrt_rn(s);
            float lp  = fmaxf(0.5f * __logf(s), -100.0f);
            float l1m = fmaxf(__logf(1.0f - pp), -100.0f);
            float cost = base + (l1m - lp) - 3.0f * __logf(iouv + 1e-8f)
                       + 1e6f + (filt ? 0.0f : 1e8f);
            unsigned long long key = (((unsigned long long)fkey(cost)) << 32) | (unsigned int)a;
            if (key < best) best = key;
        }
        #pragma unroll
        for (int o = 16; o > 0; o >>= 1) {
            unsigned long long om = __shfl_xor_sync(0xFFFFFFFFu, best, o);
            if (om < best) best = om;
        }
        if (lane == 0) {
            unsigned int aa = (unsigned int)best;
            atomicAdd(&g_mcnt[(size_t)b * A + aa], 1);
            atomicMin(&g_mfg [(size_t)b * A + aa], g);
            atomicMin(&g_amin[(size_t)b * A + aa],
                      ((best >> 32) << 6) | (unsigned long long)g);
        }
    }
}

// ---------------------------------------------------------------------------
// K3: per anchor: resolve matches, recompute pred_iou, coalesced outputs.
// Output layout (tuple order): labels | tboxes | tscores | fg | tgt_idx
// ---------------------------------------------------------------------------
__global__ __launch_bounds__(TILE) void k3(
    const float* __restrict__ pboxes, const int* __restrict__ glab,
    const float* __restrict__ gbox,   const int* __restrict__ gmask,
    float* __restrict__ out)
{
    __shared__ float4 s_box[G];
    __shared__ float4 s_aux[G];   // sx, sy, w1h1, at1
    __shared__ int    s_lab[G], s_val[G];
    __shared__ int    r_mg[TILE];
    __shared__ float  r_m [TILE];

    const int tid = threadIdx.x;
    const int b   = blockIdx.y;
    if (tid < G) {
        const float* gb = gbox + ((size_t)b * G + tid) * 4;
        float x1 = gb[0], y1 = gb[1], x2 = gb[2], y2 = gb[3];
        s_box[tid] = make_float4(x1, y1, x2, y2);
        float w1 = x2 - x1, h1 = y2 - y1;
        s_aux[tid] = make_float4(x1 + x2, y1 + y2, w1 * h1, atanf(__fdividef(w1, h1 + EPSF)));
        s_lab[tid] = glab[b * G + tid];
        s_val[tid] = gmask[b * G + tid];
    }
    __syncthreads();

    const int blockbase = blockIdx.x * TILE;
    const int count = min(TILE, A - blockbase);
    const int a = blockbase + tid;

    float piou = 0.0f;
    int   lab  = 0;
    if (tid < count) {
        const size_t ba = (size_t)b * A + a;
        const int cnt = g_mcnt[ba];
        const bool fg = (cnt > 0);
        int mg = 0;
        if (fg) {
            mg = (cnt > 1) ? (int)(g_amin[ba] & 63ull) : g_mfg[ba];
            float4 pb = *(const float4*)(pboxes + ba * 4);
            float4 bx = s_box[mg];
            float4 au = s_aux[mg];
            float w2 = pb.z - pb.x, h2 = pb.w - pb.y;
            float iw = fmaxf(fminf(bx.z, pb.z) - fmaxf(bx.x, pb.x), 0.0f);
            float ih = fmaxf(fminf(bx.w, pb.w) - fmaxf(bx.y, pb.y), 0.0f);
            float inter = iw * ih;
            float uni   = au.z + w2 * h2 - inter + EPSF;
            float iou   = __fdividef(inter, uni);
            float cw    = fmaxf(bx.z, pb.z) - fminf(bx.x, pb.x);
            float ch    = fmaxf(bx.w, pb.w) - fminf(bx.y, pb.y);
            float c2    = cw * cw + ch * ch + EPSF;
            float dx    = (pb.x + pb.z) - au.x, dy = (pb.y + pb.w) - au.y;
            float rho2  = (dx * dx + dy * dy) * 0.25f;
            float at2   = atanf(__fdividef(w2, h2 + EPSF));
            float da    = at2 - au.w;
            float v     = INV_PI2_4 * da * da;
            float alpha = __fdividef(v, v - iou + (1.0f + EPSF));
            float ciou  = iou - (__fdividef(rho2, c2) + v * alpha);
            bool filt = (g_filt[ba] != 0);
            piou = (filt && (s_val[mg] != 0)) ? fmaxf(ciou, 0.0f) : 0.0f;
        }
        lab        = s_lab[mg];
        r_mg[tid]  = fg ? mg : 0;
        r_m[tid]   = fg ? 1.0f : 0.0f;
    }
    __syncthreads();

    const size_t N  = (size_t)BS * A;
    const size_t bb = (size_t)b * A + blockbase;
    float4* os = (float4*)(out + N * 5 + bb * 80);
    const float4 z4 = make_float4(0.f, 0.f, 0.f, 0.f);

    if (count == TILE) {
        const float m = r_m[tid];
        out[bb + tid]          = (m != 0.0f) ? (float)lab : (float)C;
        out[N * 85 + bb + tid] = m;
        out[N * 86 + bb + tid] = (float)r_mg[tid];
        #pragma unroll
        for (int k = 0; k < 4; k++) {
            int i = k * TILE + tid;
            int al = i >> 2, cp = i & 3;
            out[N + bb * 4 + i] = ((const float*)s_box)[r_mg[al] * 4 + cp] * r_m[al];
        }
        #pragma unroll
        for (int k = 0; k < 20; k++) os[k * TILE + tid] = z4;
        __syncthreads();
        if (r_m[tid] != 0.0f)
            out[N * 5 + (bb + tid) * 80 + lab] = piou;
    } else {
        if (tid < count) {
            const float m = r_m[tid];
            out[bb + tid]          = (m != 0.0f) ? (float)lab : (float)C;
            out[N * 85 + bb + tid] = m;
            out[N * 86 + bb + tid] = (float)r_mg[tid];
        }
        for (int i = tid; i < count * 4; i += TILE) {
            int al = i >> 2, cp = i & 3;
            out[N + bb * 4 + i] = ((const float*)s_box)[r_mg[al] * 4 + cp] * r_m[al];
        }
        for (int i = tid; i < count * 20; i += TILE) os[i] = z4;
        __syncthreads();
        if (tid < count && r_m[tid] != 0.0f)
            out[N * 5 + (bb + tid) * 80 + lab] = piou;
    }
}

// ---------------------------------------------------------------------------
extern "C" void kernel_launch(void* const* d_in, const int* in_sizes, int n_in,
                              void* d_out, int out_size)
{
    const float* scores = (const float*)d_in[0];   // (16, 33600, 80)
    const float* pboxes = (const float*)d_in[1];   // (16, 33600, 4)
    const float* anc    = (const float*)d_in[2];   // (33600, 2)
    const int*   glab   = (const int*)  d_in[3];   // (16, 64, 1)
    const float* gbox   = (const float*)d_in[4];   // (16, 64, 4)
    const int*   gmask  = (const int*)  d_in[5];   // (16, 64, 1)
    const float* strd   = (const float*)d_in[6];   // (16, 33600, 1)
    float* out = (float*)d_out;

    kz<<<1, 1024>>>();
    dim3 gg(NCHUNK, BS);
    k1a<<<gg, TILE>>>(pboxes, anc, gbox, gmask, strd);
    k1b<<<gg, TILE>>>(scores, glab, gbox);
    k2<<<BS * G, 256>>>(scores, pboxes, glab, gbox, gmask);
    k3<<<gg, TILE>>>(pboxes, glab, gbox, gmask, out);
}

// round 11
// speedup vs baseline: 1.5031x; 1.1044x over previous
#include <cuda_runtime.h>
#include <cstdint>

#define BS 16
#define A  33600
#define G  64
#define C  80
#define EPSF 1e-7f
#define CAP 4096

#define TILE 256
#define NCHUNK ((A + TILE - 1) / TILE)

#define INV_PI2_4 0.4052847345693511f

// Scratch (device globals — no runtime allocation allowed)
__device__ unsigned long long g_key[(size_t)BS * G * CAP]; // candidate (fkey(cost)<<32 | a)
__device__ int                g_cnt[BS * G];               // candidate counts
__device__ float4             g_fpb  [(size_t)BS * A];     // filt anchors: pred box
__device__ int                g_fa   [(size_t)BS * A];     // filt anchors: anchor index
__device__ unsigned long long g_fmask[(size_t)BS * A];     // filt anchors: ic mask
__device__ int                g_fcnt[BS];                  // filt counts
__device__ unsigned char      g_filt[(size_t)BS * A];      // per-anchor anchor_filter
__device__ unsigned long long g_amin[(size_t)BS * A];      // per-anchor argmin (fkey<<6|g)
__device__ int                g_mcnt[(size_t)BS * A];      // match count per anchor
__device__ int                g_mfg [(size_t)BS * A];      // min matched g per anchor

// Monotone float -> uint32 order-preserving transform
__device__ __forceinline__ unsigned int fkey(float f) {
    unsigned int b = __float_as_uint(f);
    return b ^ ((unsigned int)((int)b >> 31) | 0x80000000u);
}

// ---------------------------------------------------------------------------
// KZ: zero small counters (single block)
// ---------------------------------------------------------------------------
__global__ void kz() {
    int i = threadIdx.x;
    if (i < BS * G) g_cnt[i] = 0;
    if (i < BS)     g_fcnt[i] = 0;
}

// ---------------------------------------------------------------------------
// K1a: per (b,a): in-center mask + compaction of filt anchors into per-batch
// lists; also zero-inits per-anchor match state.
// ---------------------------------------------------------------------------
__global__ __launch_bounds__(TILE) void k1a(
    const float* __restrict__ pboxes, const float* __restrict__ anc,
    const float* __restrict__ gbox,   const int*   __restrict__ gmask,
    const float* __restrict__ strd)
{
    __shared__ float2 s_gc[G];
    __shared__ unsigned int s_vm[2];

    const int tid = threadIdx.x;
    const int b   = blockIdx.y;

    if (tid < G) {
        const float* gb = gbox + ((size_t)b * G + tid) * 4;
        s_gc[tid] = make_float2((gb[0] + gb[2]) * 0.5f, (gb[1] + gb[3]) * 0.5f);
        unsigned int bal = __ballot_sync(0xFFFFFFFFu, gmask[b * G + tid] != 0);
        if ((tid & 31) == 0) s_vm[tid >> 5] = bal;
    }
    __syncthreads();

    const int a = blockIdx.x * TILE + tid;
    if (a >= A) return;   // warp-uniform (A % 32 == 0)

    const size_t ba = (size_t)b * A + a;
    g_mcnt[ba] = 0;
    g_mfg [ba] = 0x7FFFFFFF;
    g_amin[ba] = 0xFFFFFFFFFFFFFFFFull;

    const unsigned long long vmask =
        (unsigned long long)s_vm[0] | ((unsigned long long)s_vm[1] << 32);

    const float ax = anc[a * 2 + 0], ay = anc[a * 2 + 1];
    const float cd = strd[ba] * 2.5f;

    unsigned long long mask = 0ull;
    #pragma unroll
    for (int g = 0; g < G; g++) {
        float2 gc = s_gc[g];
        bool ic = (fabsf(ax - gc.x) < cd) && (fabsf(ay - gc.y) < cd);
        mask |= ((unsigned long long)ic) << g;
    }
    mask &= vmask;
    const bool filt = (mask != 0ull);
    g_filt[ba] = filt ? 1 : 0;

    unsigned int fm = __ballot_sync(0xFFFFFFFFu, filt);
    if (filt) {
        const float4 pb = *(const float4*)(pboxes + ba * 4);
        int lane   = tid & 31;
        int leader = __ffs(fm) - 1;
        int basei = 0;
        if (lane == leader) basei = atomicAdd(&g_fcnt[b], __popc(fm));
        basei = __shfl_sync(fm, basei, leader);
        int slot = basei + __popc(fm & ((1u << lane) - 1u));
        size_t off = (size_t)b * A + slot;
        g_fpb  [off] = pb;
        g_fa   [off] = a;
        g_fmask[off] = mask;
    }
}

// ---------------------------------------------------------------------------
// K1b: dense pass over the compacted filt-anchor list: 80-class base scan,
// sparse CIoU+cost for in-center gts, candidate emission, per-anchor argmin.
// ---------------------------------------------------------------------------
__global__ __launch_bounds__(TILE) void k1b(
    const float* __restrict__ scores, const int* __restrict__ glab,
    const float* __restrict__ gbox)
{
    __shared__ float4 s_box[G];
    __shared__ float4 s_aux[G];   // sx, sy, w1h1, at1
    __shared__ int    s_lab[G];

    const int tid = threadIdx.x;
    const int b   = blockIdx.y;

    if (tid < G) {
        const float* gb = gbox + ((size_t)b * G + tid) * 4;
        float x1 = gb[0], y1 = gb[1], x2 = gb[2], y2 = gb[3];
        s_box[tid] = make_float4(x1, y1, x2, y2);
        float w1 = x2 - x1, h1 = y2 - y1;
        s_aux[tid] = make_float4(x1 + x2, y1 + y2, w1 * h1, atanf(__fdividef(w1, h1 + EPSF)));
        s_lab[tid] = glab[b * G + tid];
    }
    __syncthreads();

    const int i = blockIdx.x * TILE + tid;
    if (i >= g_fcnt[b]) return;

    const size_t off = (size_t)b * A + i;
    const int a = g_fa[off];
    const float4 pb = g_fpb[off];
    const float w2 = pb.z - pb.x, h2 = pb.w - pb.y;
    const float w2h2 = w2 * h2;
    const float at2  = atanf(__fdividef(w2, h2 + EPSF));
    unsigned long long mm = g_fmask[off];
    const float psx = pb.x + pb.z, psy = pb.y + pb.w;

    const size_t ba = (size_t)b * A + a;
    const float* srow = scores + ba * C;

    // base = sum_c -log1p(-sqrt(s_c))
    float base = 0.0f;
    const float4* srow4 = (const float4*)srow;
    #pragma unroll
    for (int q = 0; q < C / 4; q++) {
        float4 v = srow4[q];
        float ss[4] = {v.x, v.y, v.z, v.w};
        #pragma unroll
        for (int j = 0; j < 4; j++) {
            float p = __fsqrt_rn(ss[j]);
            base -= fmaxf(__logf(1.0f - p), -100.0f);
        }
    }

    unsigned long long amin = 0xFFFFFFFFFFFFFFFFull;
    while (mm) {
        int g = __ffsll((long long)mm) - 1;
        mm &= mm - 1;
        const float4 bx = s_box[g];
        const float4 au = s_aux[g];
        float iw = fmaxf(fminf(bx.z, pb.z) - fmaxf(bx.x, pb.x), 0.0f);
        float ih = fmaxf(fminf(bx.w, pb.w) - fmaxf(bx.y, pb.y), 0.0f);
        float inter = iw * ih;
        float uni   = au.z + w2h2 - inter + EPSF;
        float iou   = __fdividef(inter, uni);
        float cw    = fmaxf(bx.z, pb.z) - fminf(bx.x, pb.x);
        float ch    = fmaxf(bx.w, pb.w) - fminf(bx.y, pb.y);
        float c2    = cw * cw + ch * ch + EPSF;
        float dx    = psx - au.x, dy = psy - au.y;
        float rho2  = (dx * dx + dy * dy) * 0.25f;
        float da    = at2 - au.w;
        float v     = INV_PI2_4 * da * da;
        float alpha = __fdividef(v, v - iou + (1.0f + EPSF));
        float ciou  = iou - (__fdividef(rho2, c2) + v * alpha);
        float iouv  = fmaxf(ciou, 0.0f);

        float s   = srow[s_lab[g]];
        float p   = __fsqrt_rn(s);
        float lp  = fmaxf(0.5f * __logf(s), -100.0f);
        float l1m = fmaxf(__logf(1.0f - p), -100.0f);

        float cost = base + (l1m - lp) - 3.0f * __logf(iouv + 1e-8f);

        unsigned int k32 = fkey(cost);
        unsigned long long pk = (((unsigned long long)k32) << 6) | (unsigned int)g;
        if (pk < amin) amin = pk;

        int slot = atomicAdd(&g_cnt[b * G + g], 1);
        if (slot < CAP)
            g_key[(size_t)(b * G + g) * CAP + slot] =
                (((unsigned long long)k32) << 32) | (unsigned int)a;
    }
    g_amin[ba] = amin;
}

// ---------------------------------------------------------------------------
// K2: block per (b,g). Phase A: pruned scan -> per-thread top-10 -> smem
// (transposed, conflict-free) -> ONE barrier -> warp 0 merges with static
// register indexing only (owner-lane shift-down, no dynamic top[p]).
// Phase B (warp 0): dyn_k-th smallest cost key -> T; mark matches.
// ---------------------------------------------------------------------------
__global__ __launch_bounds__(256, 4) void k2(
    const float* __restrict__ scores, const float* __restrict__ pboxes,
    const int* __restrict__ glab, const float* __restrict__ gbox,
    const int* __restrict__ gmask)
{
    __shared__ float fc[10 * 256];   // transposed: fc[j*256 + tid]

    const int bg  = blockIdx.x;
    const int tid = threadIdx.x;
    const int lane = tid & 31, wid = tid >> 5;
    const int b = bg >> 6, g = bg & 63;
    if (gmask[bg] == 0) return;

    const float* gb = gbox + (size_t)bg * 4;
    const float x1 = gb[0], y1 = gb[1], x2 = gb[2], y2 = gb[3];
    const float w1 = x2 - x1, h1 = y2 - y1, w1h1 = w1 * h1;
    const float at1 = atanf(__fdividef(w1, h1 + EPSF));
    const float sx = x1 + x2, sy = y1 + y2;

    // ---- Phase A: pruned scan, per-thread top-10 ----
    const int n_f = g_fcnt[b];
    float top[10];
    #pragma unroll
    for (int j = 0; j < 10; j++) top[j] = 0.0f;   // iouv >= 0; zero-padding exact

    for (int i = tid; i < n_f; i += 256) {
        float4 pb = g_fpb[(size_t)b * A + i];
        float w2 = pb.z - pb.x, h2 = pb.w - pb.y;
        float iw = fmaxf(fminf(x2, pb.z) - fmaxf(x1, pb.x), 0.0f);
        float ih = fmaxf(fminf(y2, pb.w) - fmaxf(y1, pb.y), 0.0f);
        float inter = iw * ih;
        float uni   = w1h1 + w2 * h2 - inter + EPSF;
        if (inter > top[9] * uni) {       // exact: iou > top[9]; implies inter > 0
            float iou   = __fdividef(inter, uni);
            float cw    = fmaxf(x2, pb.z) - fminf(x1, pb.x);
            float ch    = fmaxf(y2, pb.w) - fminf(y1, pb.y);
            float c2    = cw * cw + ch * ch + EPSF;
            float dx    = (pb.x + pb.z) - sx, dy = (pb.y + pb.w) - sy;
            float rho2  = (dx * dx + dy * dy) * 0.25f;
            float at2   = atanf(__fdividef(w2, h2 + EPSF));
            float da    = at2 - at1;
            float v     = INV_PI2_4 * da * da;
            float alpha = __fdividef(v, v - iou + (1.0f + EPSF));
            float ciou  = iou - (__fdividef(rho2, c2) + v * alpha);
            float iouv  = fmaxf(ciou, 0.0f);
            if (iouv > top[9]) {
                top[9] = iouv;
                #pragma unroll
                for (int j = 8; j >= 0; j--)
                    if (top[j + 1] > top[j]) { float t = top[j]; top[j] = top[j + 1]; top[j + 1] = t; }
            }
        }
    }
    #pragma unroll
    for (int j = 0; j < 10; j++) fc[j * 256 + tid] = top[j];
    __syncthreads();
    if (wid != 0) return;

    // ---- Warp 0: merge 2560 values. Lane owns threads {lane, lane+32, ...}
    // (conflict-free LDS). Static insertion; owner-lane static shift-down. ----
    float loc[10];
    #pragma unroll
    for (int j = 0; j < 10; j++) loc[j] = 0.0f;
    #pragma unroll
    for (int k = 0; k < 8; k++) {
        #pragma unroll
        for (int j = 0; j < 10; j++) {
            float v = fc[j * 256 + k * 32 + lane];
            if (v > loc[9]) {
                loc[9] = v;
                #pragma unroll
                for (int t = 8; t >= 0; t--)
                    if (loc[t + 1] > loc[t]) { float tt = loc[t]; loc[t] = loc[t + 1]; loc[t + 1] = tt; }
            }
        }
    }
    float sum = 0.0f;
    #pragma unroll
    for (int r = 0; r < 10; r++) {
        unsigned long long key =
            (((unsigned long long)__float_as_uint(loc[0])) << 6) | (unsigned int)lane;
        #pragma unroll
        for (int o = 16; o > 0; o >>= 1) {
            unsigned long long ok = __shfl_xor_sync(0xFFFFFFFFu, key, o);
            if (ok > key) key = ok;
        }
        sum += __uint_as_float((unsigned int)(key >> 6));
        if ((int)(key & 63ull) == lane) {        // static shift-down
            #pragma unroll
            for (int t = 0; t < 9; t++) loc[t] = loc[t + 1];
            loc[9] = 0.0f;
        }
    }
    const int dynk = max((int)(sum + 0.5f), 1);

    // ---- Phase B (warp 0): dyn_k-th smallest candidate key -> T; mark ----
    const int n = min(g_cnt[bg], CAP);
    const unsigned long long* kl = g_key + (size_t)bg * CAP;

    if (n > 0) {
        unsigned long long bot[10];
        #pragma unroll
        for (int j = 0; j < 10; j++) bot[j] = 0xFFFFFFFFFFFFFFFFull;
        for (int i = lane; i < n; i += 32) {
            unsigned long long key = kl[i];
            if (key < bot[9]) {
                bot[9] = key;
                #pragma unroll
                for (int j = 8; j >= 0; j--)
                    if (bot[j + 1] < bot[j]) { unsigned long long t = bot[j]; bot[j] = bot[j + 1]; bot[j + 1] = t; }
            }
        }
        unsigned long long T = 0xFFFFFFFFFFFFFFFFull;
        for (int r = 0; r < dynk; r++) {
            unsigned long long m = bot[0];
            #pragma unroll
            for (int o = 16; o > 0; o >>= 1) {
                unsigned long long om = __shfl_xor_sync(0xFFFFFFFFu, m, o);
                if (om < m) m = om;
            }
            T = m;
            if (bot[0] == m) {                   // keys unique; static shift-down
                #pragma unroll
                for (int t = 0; t < 9; t++) bot[t] = bot[t + 1];
                bot[9] = 0xFFFFFFFFFFFFFFFFull;
            }
        }
        for (int i = lane; i < n; i += 32) {
            unsigned long long key = kl[i];
            if (key <= T) {
                unsigned int aa = (unsigned int)key;
                atomicAdd(&g_mcnt[(size_t)b * A + aa], 1);
                atomicMin(&g_mfg [(size_t)b * A + aa], g);
            }
        }
    } else {
        // Fallback (statistically unreachable): warp-level global row min.
        const int lab = glab[bg];
        unsigned long long best = 0xFFFFFFFFFFFFFFFFull;
        for (int a = lane; a < A; a += 32) {
            const size_t ba = (size_t)b * A + a;
            float4 pb = *(const float4*)(pboxes + ba * 4);
            float w2 = pb.z - pb.x, h2 = pb.w - pb.y;
            float iw = fmaxf(fminf(x2, pb.z) - fmaxf(x1, pb.x), 0.0f);
            float ih = fmaxf(fminf(y2, pb.w) - fmaxf(y1, pb.y), 0.0f);
            float inter = iw * ih;
            float uni   = w1h1 + w2 * h2 - inter + EPSF;
            float iou   = __fdividef(inter, uni);
            float cw    = fmaxf(x2, pb.z) - fminf(x1, pb.x);
            float ch    = fmaxf(y2, pb.w) - fminf(y1, pb.y);
            float c2    = cw * cw + ch * ch + EPSF;
            float dx    = (pb.x + pb.z) - sx, dy = (pb.y + pb.w) - sy;
            float rho2  = (dx * dx + dy * dy) * 0.25f;
            float at2   = atanf(__fdividef(w2, h2 + EPSF));
            float da    = at2 - at1;
            float v     = INV_PI2_4 * da * da;
            float alpha = __fdividef(v, v - iou + (1.0f + EPSF));
            float ciou  = iou - (__fdividef(rho2, c2) + v * alpha);

            bool filt = g_filt[ba] != 0;
            float iouv = filt ? fmaxf(ciou, 0.0f) : 0.0f;

            float base = 0.0f;
            const float4* s4 = (const float4*)(scores + ba * C);
            #pragma unroll 4
            for (int qq = 0; qq < C / 4; qq++) {
                float4 vv = s4[qq];
                base -= fmaxf(__logf(1.0f - __fsqrt_rn(vv.x)), -100.0f);
                base -= fmaxf(__logf(1.0f - __fsqrt_rn(vv.y)), -100.0f);
                base -= fmaxf(__logf(1.0f - __fsqrt_rn(vv.z)), -100.0f);
                base -= fmaxf(__logf(1.0f - __fsqrt_rn(vv.w)), -100.0f);
            }
            float s = scores[ba * C + lab];
            float pp = __fsqrt_rn(s);
            float lp  = fmaxf(0.5f * __logf(s), -100.0f);
            float l1m = fmaxf(__logf(1.0f - pp), -100.0f);
            float cost = base + (l1m - lp) - 3.0f * __logf(iouv + 1e-8f)
                       + 1e6f + (filt ? 0.0f : 1e8f);
            unsigned long long key = (((unsigned long long)fkey(cost)) << 32) | (unsigned int)a;
            if (key < best) best = key;
        }
        #pragma unroll
        for (int o = 16; o > 0; o >>= 1) {
            unsigned long long om = __shfl_xor_sync(0xFFFFFFFFu, best, o);
            if (om < best) best = om;
        }
        if (lane == 0) {
            unsigned int aa = (unsigned int)best;
            atomicAdd(&g_mcnt[(size_t)b * A + aa], 1);
            atomicMin(&g_mfg [(size_t)b * A + aa], g);
            atomicMin(&g_amin[(size_t)b * A + aa],
                      ((best >> 32) << 6) | (unsigned long long)g);
        }
    }
}

// ---------------------------------------------------------------------------
// K3: per anchor: resolve matches, recompute pred_iou, coalesced outputs.
// Output layout (tuple order): labels | tboxes | tscores | fg | tgt_idx
// ---------------------------------------------------------------------------
__global__ __launch_bounds__(TILE) void k3(
    const float* __restrict__ pboxes, const int* __restrict__ glab,
    const float* __restrict__ gbox,   const int* __restrict__ gmask,
    float* __restrict__ out)
{
    __shared__ float4 s_box[G];
    __shared__ float4 s_aux[G];   // sx, sy, w1h1, at1
    __shared__ int    s_lab[G], s_val[G];
    __shared__ int    r_mg[TILE];
    __shared__ float  r_m [TILE];

    const int tid = threadIdx.x;
    const int b   = blockIdx.y;
    if (tid < G) {
        const float* gb = gbox + ((size_t)b * G + tid) * 4;
        float x1 = gb[0], y1 = gb[1], x2 = gb[2], y2 = gb[3];
        s_box[tid] = make_float4(x1, y1, x2, y2);
        float w1 = x2 - x1, h1 = y2 - y1;
        s_aux[tid] = make_float4(x1 + x2, y1 + y2, w1 * h1, atanf(__fdividef(w1, h1 + EPSF)));
        s_lab[tid] = glab[b * G + tid];
        s_val[tid] = gmask[b * G + tid];
    }
    __syncthreads();

    const int blockbase = blockIdx.x * TILE;
    const int count = min(TILE, A - blockbase);
    const int a = blockbase + tid;

    float piou = 0.0f;
    int   lab  = 0;
    if (tid < count) {
        const size_t ba = (size_t)b * A + a;
        const int cnt = g_mcnt[ba];
        const bool fg = (cnt > 0);
        int mg = 0;
        if (fg) {
            mg = (cnt > 1) ? (int)(g_amin[ba] & 63ull) : g_mfg[ba];
            float4 pb = *(const float4*)(pboxes + ba * 4);
            float4 bx = s_box[mg];
            float4 au = s_aux[mg];
            float w2 = pb.z - pb.x, h2 = pb.w - pb.y;
            float iw = fmaxf(fminf(bx.z, pb.z) - fmaxf(bx.x, pb.x), 0.0f);
            float ih = fmaxf(fminf(bx.w, pb.w) - fmaxf(bx.y, pb.y), 0.0f);
            float inter = iw * ih;
            float uni   = au.z + w2 * h2 - inter + EPSF;
            float iou   = __fdividef(inter, uni);
            float cw    = fmaxf(bx.z, pb.z) - fminf(bx.x, pb.x);
            float ch    = fmaxf(bx.w, pb.w) - fminf(bx.y, pb.y);
            float c2    = cw * cw + ch * ch + EPSF;
            float dx    = (pb.x + pb.z) - au.x, dy = (pb.y + pb.w) - au.y;
            float rho2  = (dx * dx + dy * dy) * 0.25f;
            float at2   = atanf(__fdividef(w2, h2 + EPSF));
            float da    = at2 - au.w;
            float v     = INV_PI2_4 * da * da;
            float alpha = __fdividef(v, v - iou + (1.0f + EPSF));
            float ciou  = iou - (__fdividef(rho2, c2) + v * alpha);
            bool filt = (g_filt[ba] != 0);
            piou = (filt && (s_val[mg] != 0)) ? fmaxf(ciou, 0.0f) : 0.0f;
        }
        lab        = s_lab[mg];
        r_mg[tid]  = fg ? mg : 0;
        r_m[tid]   = fg ? 1.0f : 0.0f;
    }
    __syncthreads();

    const size_t N  = (size_t)BS * A;
    const size_t bb = (size_t)b * A + blockbase;
    float4* os = (float4*)(out + N * 5 + bb * 80);
    const float4 z4 = make_float4(0.f, 0.f, 0.f, 0.f);

    if (count == TILE) {
        const float m = r_m[tid];
        out[bb + tid]          = (m != 0.0f) ? (float)lab : (float)C;
        out[N * 85 + bb + tid] = m;
        out[N * 86 + bb + tid] = (float)r_mg[tid];
        #pragma unroll
        for (int k = 0; k < 4; k++) {
            int i = k * TILE + tid;
            int al = i >> 2, cp = i & 3;
            out[N + bb * 4 + i] = ((const float*)s_box)[r_mg[al] * 4 + cp] * r_m[al];
        }
        #pragma unroll
        for (int k = 0; k < 20; k++) os[k * TILE + tid] = z4;
        __syncthreads();
        if (r_m[tid] != 0.0f)
            out[N * 5 + (bb + tid) * 80 + lab] = piou;
    } else {
        if (tid < count) {
            const float m = r_m[tid];
            out[bb + tid]          = (m != 0.0f) ? (float)lab : (float)C;
            out[N * 85 + bb + tid] = m;
            out[N * 86 + bb + tid] = (float)r_mg[tid];
        }
        for (int i = tid; i < count * 4; i += TILE) {
            int al = i >> 2, cp = i & 3;
            out[N + bb * 4 + i] = ((const float*)s_box)[r_mg[al] * 4 + cp] * r_m[al];
        }
        for (int i = tid; i < count * 20; i += TILE) os[i] = z4;
        __syncthreads();
        if (tid < count && r_m[tid] != 0.0f)
            out[N * 5 + (bb + tid) * 80 + lab] = piou;
    }
}

// ---------------------------------------------------------------------------
extern "C" void kernel_launch(void* const* d_in, const int* in_sizes, int n_in,
                              void* d_out, int out_size)
{
    const float* scores = (const float*)d_in[0];   // (16, 33600, 80)
    const float* pboxes = (const float*)d_in[1];   // (16, 33600, 4)
    const float* anc    = (const float*)d_in[2];   // (33600, 2)
    const int*   glab   = (const int*)  d_in[3];   // (16, 64, 1)
    const float* gbox   = (const float*)d_in[4];   // (16, 64, 4)
    const int*   gmask  = (const int*)  d_in[5];   // (16, 64, 1)
    const float* strd   = (const float*)d_in[6];   // (16, 33600, 1)
    float* out = (float*)d_out;

    kz<<<1, 1024>>>();
    dim3 gg(NCHUNK, BS);
    k1a<<<gg, TILE>>>(pboxes, anc, gbox, gmask, strd);
    k1b<<<gg, TILE>>>(scores, glab, gbox);
    k2<<<BS * G, 256>>>(scores, pboxes, glab, gbox, gmask);
    k3<<<gg, TILE>>>(pboxes, glab, gbox, gmask, out);
}

// round 12
// speedup vs baseline: 1.6249x; 1.0810x over previous
#include <cuda_runtime.h>
#include <cstdint>

#define BS 16
#define A  33600
#define G  64
#define C  80
#define EPSF 1e-7f
#define CAP 4096

#define TILE 256
#define NCHUNK ((A + TILE - 1) / TILE)

#define INV_PI2_4 0.4052847345693511f

// Scratch (device globals — no runtime allocation allowed)
__device__ unsigned long long g_key[(size_t)BS * G * CAP]; // candidate (fkey(cost)<<32 | a)
__device__ int                g_cnt[BS * G];               // candidate counts
__device__ float4             g_fpb  [(size_t)BS * A];     // filt anchors: pred box
__device__ int                g_fa   [(size_t)BS * A];     // filt anchors: anchor index
__device__ unsigned long long g_fmask[(size_t)BS * A];     // filt anchors: ic mask
__device__ int                g_fcnt[BS];                  // filt counts
__device__ unsigned char      g_filt[(size_t)BS * A];      // per-anchor anchor_filter
__device__ unsigned long long g_amin[(size_t)BS * A];      // per-anchor argmin (fkey<<6|g)
__device__ int                g_mcnt[(size_t)BS * A];      // match count per anchor
__device__ int                g_mfg [(size_t)BS * A];      // min matched g per anchor

// Monotone float -> uint32 order-preserving transform
__device__ __forceinline__ unsigned int fkey(float f) {
    unsigned int b = __float_as_uint(f);
    return b ^ ((unsigned int)((int)b >> 31) | 0x80000000u);
}

// ---------------------------------------------------------------------------
// KZ: zero small counters (single block)
// ---------------------------------------------------------------------------
__global__ void kz() {
    int i = threadIdx.x;
    if (i < BS * G) g_cnt[i] = 0;
    if (i < BS)     g_fcnt[i] = 0;
}

// ---------------------------------------------------------------------------
// K1a: per (b,a): in-center mask + compaction of filt anchors into per-batch
// lists; also zero-inits per-anchor match state.
// ---------------------------------------------------------------------------
__global__ __launch_bounds__(TILE) void k1a(
    const float* __restrict__ pboxes, const float* __restrict__ anc,
    const float* __restrict__ gbox,   const int*   __restrict__ gmask,
    const float* __restrict__ strd)
{
    __shared__ float2 s_gc[G];
    __shared__ unsigned int s_vm[2];

    const int tid = threadIdx.x;
    const int b   = blockIdx.y;

    if (tid < G) {
        const float* gb = gbox + ((size_t)b * G + tid) * 4;
        s_gc[tid] = make_float2((gb[0] + gb[2]) * 0.5f, (gb[1] + gb[3]) * 0.5f);
        unsigned int bal = __ballot_sync(0xFFFFFFFFu, gmask[b * G + tid] != 0);
        if ((tid & 31) == 0) s_vm[tid >> 5] = bal;
    }
    __syncthreads();

    const int a = blockIdx.x * TILE + tid;
    if (a >= A) return;   // warp-uniform (A % 32 == 0)

    const size_t ba = (size_t)b * A + a;
    g_mcnt[ba] = 0;
    g_mfg [ba] = 0x7FFFFFFF;
    g_amin[ba] = 0xFFFFFFFFFFFFFFFFull;

    const unsigned long long vmask =
        (unsigned long long)s_vm[0] | ((unsigned long long)s_vm[1] << 32);

    const float ax = anc[a * 2 + 0], ay = anc[a * 2 + 1];
    const float cd = strd[ba] * 2.5f;

    unsigned long long mask = 0ull;
    #pragma unroll
    for (int g = 0; g < G; g++) {
        float2 gc = s_gc[g];
        bool ic = (fabsf(ax - gc.x) < cd) && (fabsf(ay - gc.y) < cd);
        mask |= ((unsigned long long)ic) << g;
    }
    mask &= vmask;
    const bool filt = (mask != 0ull);
    g_filt[ba] = filt ? 1 : 0;

    unsigned int fm = __ballot_sync(0xFFFFFFFFu, filt);
    if (filt) {
        const float4 pb = *(const float4*)(pboxes + ba * 4);
        int lane   = tid & 31;
        int leader = __ffs(fm) - 1;
        int basei = 0;
        if (lane == leader) basei = atomicAdd(&g_fcnt[b], __popc(fm));
        basei = __shfl_sync(fm, basei, leader);
        int slot = basei + __popc(fm & ((1u << lane) - 1u));
        size_t off = (size_t)b * A + slot;
        g_fpb  [off] = pb;
        g_fa   [off] = a;
        g_fmask[off] = mask;
    }
}

// ---------------------------------------------------------------------------
// K1b: dense pass over the compacted filt-anchor list: 80-class base scan,
// sparse CIoU+cost for in-center gts, candidate emission, per-anchor argmin.
// ---------------------------------------------------------------------------
__global__ __launch_bounds__(TILE) void k1b(
    const float* __restrict__ scores, const int* __restrict__ glab,
    const float* __restrict__ gbox)
{
    __shared__ float4 s_box[G];
    __shared__ float4 s_aux[G];   // sx, sy, w1h1, at1
    __shared__ int    s_lab[G];

    const int tid = threadIdx.x;
    const int b   = blockIdx.y;

    if (tid < G) {
        const float* gb = gbox + ((size_t)b * G + tid) * 4;
        float x1 = gb[0], y1 = gb[1], x2 = gb[2], y2 = gb[3];
        s_box[tid] = make_float4(x1, y1, x2, y2);
        float w1 = x2 - x1, h1 = y2 - y1;
        s_aux[tid] = make_float4(x1 + x2, y1 + y2, w1 * h1, atanf(__fdividef(w1, h1 + EPSF)));
        s_lab[tid] = glab[b * G + tid];
    }
    __syncthreads();

    const int i = blockIdx.x * TILE + tid;
    if (i >= g_fcnt[b]) return;

    const size_t off = (size_t)b * A + i;
    const int a = g_fa[off];
    const float4 pb = g_fpb[off];
    const float w2 = pb.z - pb.x, h2 = pb.w - pb.y;
    const float w2h2 = w2 * h2;
    const float at2  = atanf(__fdividef(w2, h2 + EPSF));
    unsigned long long mm = g_fmask[off];
    const float psx = pb.x + pb.z, psy = pb.y + pb.w;

    const size_t ba = (size_t)b * A + a;
    const float* srow = scores + ba * C;

    // base = sum_c -log1p(-sqrt(s_c))
    float base = 0.0f;
    const float4* srow4 = (const float4*)srow;
    #pragma unroll
    for (int q = 0; q < C / 4; q++) {
        float4 v = srow4[q];
        float ss[4] = {v.x, v.y, v.z, v.w};
        #pragma unroll
        for (int j = 0; j < 4; j++) {
            float p = __fsqrt_rn(ss[j]);
            base -= fmaxf(__logf(1.0f - p), -100.0f);
        }
    }

    unsigned long long amin = 0xFFFFFFFFFFFFFFFFull;
    while (mm) {
        int g = __ffsll((long long)mm) - 1;
        mm &= mm - 1;
        const float4 bx = s_box[g];
        const float4 au = s_aux[g];
        float iw = fmaxf(fminf(bx.z, pb.z) - fmaxf(bx.x, pb.x), 0.0f);
        float ih = fmaxf(fminf(bx.w, pb.w) - fmaxf(bx.y, pb.y), 0.0f);
        float inter = iw * ih;
        float uni   = au.z + w2h2 - inter + EPSF;
        float iou   = __fdividef(inter, uni);
        float cw    = fmaxf(bx.z, pb.z) - fminf(bx.x, pb.x);
        float ch    = fmaxf(bx.w, pb.w) - fminf(bx.y, pb.y);
        float c2    = cw * cw + ch * ch + EPSF;
        float dx    = psx - au.x, dy = psy - au.y;
        float rho2  = (dx * dx + dy * dy) * 0.25f;
        float da    = at2 - au.w;
        float v     = INV_PI2_4 * da * da;
        float alpha = __fdividef(v, v - iou + (1.0f + EPSF));
        float ciou  = iou - (__fdividef(rho2, c2) + v * alpha);
        float iouv  = fmaxf(ciou, 0.0f);

        float s   = srow[s_lab[g]];
        float p   = __fsqrt_rn(s);
        float lp  = fmaxf(0.5f * __logf(s), -100.0f);
        float l1m = fmaxf(__logf(1.0f - p), -100.0f);

        float cost = base + (l1m - lp) - 3.0f * __logf(iouv + 1e-8f);

        unsigned int k32 = fkey(cost);
        unsigned long long pk = (((unsigned long long)k32) << 6) | (unsigned int)g;
        if (pk < amin) amin = pk;

        int slot = atomicAdd(&g_cnt[b * G + g], 1);
        if (slot < CAP)
            g_key[(size_t)(b * G + g) * CAP + slot] =
                (((unsigned long long)k32) << 32) | (unsigned int)a;
    }
    g_amin[ba] = amin;
}

// ---------------------------------------------------------------------------
// K2: block per (b,g). Phase A: pruned scan -> per-thread top-10 -> parallel
// smem merge tree (8 levels, static insertion, all warps active) -> dyn_k.
// Phase B (warp 0): dyn_k-th smallest cost key -> T; mark matches.
// Pruning exact: iouv <= iou, and iou > t  <=>  inter > t*uni.
// ---------------------------------------------------------------------------
__global__ __launch_bounds__(256, 6) void k2(
    const float* __restrict__ scores, const float* __restrict__ pboxes,
    const int* __restrict__ glab, const float* __restrict__ gbox,
    const int* __restrict__ gmask)
{
    __shared__ float fc[10 * 256];   // transposed: fc[j*256 + tid]
    __shared__ int   s_dynk;

    const int bg  = blockIdx.x;
    const int tid = threadIdx.x;
    const int b = bg >> 6, g = bg & 63;
    if (gmask[bg] == 0) return;

    const float* gb = gbox + (size_t)bg * 4;
    const float x1 = gb[0], y1 = gb[1], x2 = gb[2], y2 = gb[3];
    const float w1 = x2 - x1, h1 = y2 - y1, w1h1 = w1 * h1;
    const float at1 = atanf(__fdividef(w1, h1 + EPSF));
    const float sx = x1 + x2, sy = y1 + y2;

    // ---- Phase A: pruned scan, per-thread top-10 ----
    const int n_f = g_fcnt[b];
    float top[10];
    #pragma unroll
    for (int j = 0; j < 10; j++) top[j] = 0.0f;   // iouv >= 0; zero-padding exact

    for (int i = tid; i < n_f; i += 256) {
        float4 pb = g_fpb[(size_t)b * A + i];
        float w2 = pb.z - pb.x, h2 = pb.w - pb.y;
        float iw = fmaxf(fminf(x2, pb.z) - fmaxf(x1, pb.x), 0.0f);
        float ih = fmaxf(fminf(y2, pb.w) - fmaxf(y1, pb.y), 0.0f);
        float inter = iw * ih;
        float uni   = w1h1 + w2 * h2 - inter + EPSF;
        if (inter > top[9] * uni) {       // exact: iou > top[9]; implies inter > 0
            float iou   = __fdividef(inter, uni);
            float cw    = fmaxf(x2, pb.z) - fminf(x1, pb.x);
            float ch    = fmaxf(y2, pb.w) - fminf(y1, pb.y);
            float c2    = cw * cw + ch * ch + EPSF;
            float dx    = (pb.x + pb.z) - sx, dy = (pb.y + pb.w) - sy;
            float rho2  = (dx * dx + dy * dy) * 0.25f;
            float at2   = atanf(__fdividef(w2, h2 + EPSF));
            float da    = at2 - at1;
            float v     = INV_PI2_4 * da * da;
            float alpha = __fdividef(v, v - iou + (1.0f + EPSF));
            float ciou  = iou - (__fdividef(rho2, c2) + v * alpha);
            float iouv  = fmaxf(ciou, 0.0f);
            if (iouv > top[9]) {
                top[9] = iouv;
                #pragma unroll
                for (int j = 8; j >= 0; j--)
                    if (top[j + 1] > top[j]) { float t = top[j]; top[j] = top[j + 1]; top[j + 1] = t; }
            }
        }
    }
    #pragma unroll
    for (int j = 0; j < 10; j++) fc[j * 256 + tid] = top[j];
    __syncthreads();

    // ---- Parallel merge tree: thread tid<s inserts sorted list at tid+s ----
    for (int s = 128; s >= 1; s >>= 1) {
        if (tid < s) {
            #pragma unroll
            for (int j = 0; j < 10; j++) {
                float v = fc[j * 256 + tid + s];
                if (v > top[9]) {
                    top[9] = v;
                    #pragma unroll
                    for (int t = 8; t >= 0; t--)
                        if (top[t + 1] > top[t]) { float tt = top[t]; top[t] = top[t + 1]; top[t + 1] = tt; }
                }
            }
            #pragma unroll
            for (int j = 0; j < 10; j++) fc[j * 256 + tid] = top[j];
        }
        __syncthreads();
    }
    if (tid == 0) {
        float sum = 0.0f;
        #pragma unroll
        for (int j = 0; j < 10; j++) sum += top[j];   // descending order = top_k sum order
        s_dynk = max((int)(sum + 0.5f), 1);
    }
    __syncthreads();
    const int dynk = s_dynk;

    if (tid >= 32) return;
    const int lane = tid;

    // ---- Phase B (warp 0): dyn_k-th smallest candidate key -> T; mark ----
    const int n = min(g_cnt[bg], CAP);
    const unsigned long long* kl = g_key + (size_t)bg * CAP;

    if (n > 0) {
        unsigned long long bot[10];
        #pragma unroll
        for (int j = 0; j < 10; j++) bot[j] = 0xFFFFFFFFFFFFFFFFull;
        for (int i = lane; i < n; i += 32) {
            unsigned long long key = kl[i];
            if (key < bot[9]) {
                bot[9] = key;
                #pragma unroll
                for (int j = 8; j >= 0; j--)
                    if (bot[j + 1] < bot[j]) { unsigned long long t = bot[j]; bot[j] = bot[j + 1]; bot[j + 1] = t; }
            }
        }
        unsigned long long T = 0xFFFFFFFFFFFFFFFFull;
        for (int r = 0; r < dynk; r++) {
            unsigned long long m = bot[0];
            #pragma unroll
            for (int o = 16; o > 0; o >>= 1) {
                unsigned long long om = __shfl_xor_sync(0xFFFFFFFFu, m, o);
                if (om < m) m = om;
            }
            T = m;
            if (bot[0] == m) {                   // keys unique; static shift-down
                #pragma unroll
                for (int t = 0; t < 9; t++) bot[t] = bot[t + 1];
                bot[9] = 0xFFFFFFFFFFFFFFFFull;
            }
        }
        for (int i = lane; i < n; i += 32) {
            unsigned long long key = kl[i];
            if (key <= T) {
                unsigned int aa = (unsigned int)key;
                atomicAdd(&g_mcnt[(size_t)b * A + aa], 1);
                atomicMin(&g_mfg [(size_t)b * A + aa], g);
            }
        }
    } else {
        // Fallback (statistically unreachable): warp-level global row min.
        const int lab = glab[bg];
        unsigned long long best = 0xFFFFFFFFFFFFFFFFull;
        for (int a = lane; a < A; a += 32) {
            const size_t ba = (size_t)b * A + a;
            float4 pb = *(const float4*)(pboxes + ba * 4);
            float w2 = pb.z - pb.x, h2 = pb.w - pb.y;
            float iw = fmaxf(fminf(x2, pb.z) - fmaxf(x1, pb.x), 0.0f);
            float ih = fmaxf(fminf(y2, pb.w) - fmaxf(y1, pb.y), 0.0f);
            float inter = iw * ih;
            float uni   = w1h1 + w2 * h2 - inter + EPSF;
            float iou   = __fdividef(inter, uni);
            float cw    = fmaxf(x2, pb.z) - fminf(x1, pb.x);
            float ch    = fmaxf(y2, pb.w) - fminf(y1, pb.y);
            float c2    = cw * cw + ch * ch + EPSF;
            float dx    = (pb.x + pb.z) - sx, dy = (pb.y + pb.w) - sy;
            float rho2  = (dx * dx + dy * dy) * 0.25f;
            float at2   = atanf(__fdividef(w2, h2 + EPSF));
            float da    = at2 - at1;
            float v     = INV_PI2_4 * da * da;
            float alpha = __fdividef(v, v - iou + (1.0f + EPSF));
            float ciou  = iou - (__fdividef(rho2, c2) + v * alpha);

            bool filt = g_filt[ba] != 0;
            float iouv = filt ? fmaxf(ciou, 0.0f) : 0.0f;

            float base = 0.0f;
            const float4* s4 = (const float4*)(scores + ba * C);
            #pragma unroll 4
            for (int qq = 0; qq < C / 4; qq++) {
                float4 vv = s4[qq];
                base -= fmaxf(__logf(1.0f - __fsqrt_rn(vv.x)), -100.0f);
                base -= fmaxf(__logf(1.0f - __fsqrt_rn(vv.y)), -100.0f);
                base -= fmaxf(__logf(1.0f - __fsqrt_rn(vv.z)), -100.0f);
                base -= fmaxf(__logf(1.0f - __fsqrt_rn(vv.w)), -100.0f);
            }
            float s = scores[ba * C + lab];
            float pp = __fsqrt_rn(s);
            float lp  = fmaxf(0.5f * __logf(s), -100.0f);
            float l1m = fmaxf(__logf(1.0f - pp), -100.0f);
            float cost = base + (l1m - lp) - 3.0f * __logf(iouv + 1e-8f)
                       + 1e6f + (filt ? 0.0f : 1e8f);
            unsigned long long key = (((unsigned long long)fkey(cost)) << 32) | (unsigned int)a;
            if (key < best) best = key;
        }
        #pragma unroll
        for (int o = 16; o > 0; o >>= 1) {
            unsigned long long om = __shfl_xor_sync(0xFFFFFFFFu, best, o);
            if (om < best) best = om;
        }
        if (lane == 0) {
            unsigned int aa = (unsigned int)best;
            atomicAdd(&g_mcnt[(size_t)b * A + aa], 1);
            atomicMin(&g_mfg [(size_t)b * A + aa], g);
            atomicMin(&g_amin[(size_t)b * A + aa],
                      ((best >> 32) << 6) | (unsigned long long)g);
        }
    }
}

// ---------------------------------------------------------------------------
// K3: per anchor: resolve matches, recompute pred_iou, coalesced outputs.
// Output layout (tuple order): labels | tboxes | tscores | fg | tgt_idx
// ---------------------------------------------------------------------------
__global__ __launch_bounds__(TILE) void k3(
    const float* __restrict__ pboxes, const int* __restrict__ glab,
    const float* __restrict__ gbox,   const int* __restrict__ gmask,
    float* __restrict__ out)
{
    __shared__ float4 s_box[G];
    __shared__ float4 s_aux[G];   // sx, sy, w1h1, at1
    __shared__ int    s_lab[G], s_val[G];
    __shared__ int    r_mg[TILE];
    __shared__ float  r_m [TILE];

    const int tid = threadIdx.x;
    const int b   = blockIdx.y;
    if (tid < G) {
        const float* gb = gbox + ((size_t)b * G + tid) * 4;
        float x1 = gb[0], y1 = gb[1], x2 = gb[2], y2 = gb[3];
        s_box[tid] = make_float4(x1, y1, x2, y2);
        float w1 = x2 - x1, h1 = y2 - y1;
        s_aux[tid] = make_float4(x1 + x2, y1 + y2, w1 * h1, atanf(__fdividef(w1, h1 + EPSF)));
        s_lab[tid] = glab[b * G + tid];
        s_val[tid] = gmask[b * G + tid];
    }
    __syncthreads();

    const int blockbase = blockIdx.x * TILE;
    const int count = min(TILE, A - blockbase);
    const int a = blockbase + tid;

    float piou = 0.0f;
    int   lab  = 0;
    if (tid < count) {
        const size_t ba = (size_t)b * A + a;
        const int cnt = g_mcnt[ba];
        const bool fg = (cnt > 0);
        int mg = 0;
        if (fg) {
            mg = (cnt > 1) ? (int)(g_amin[ba] & 63ull) : g_mfg[ba];
            float4 pb = *(const float4*)(pboxes + ba * 4);
            float4 bx = s_box[mg];
            float4 au = s_aux[mg];
            float w2 = pb.z - pb.x, h2 = pb.w - pb.y;
            float iw = fmaxf(fminf(bx.z, pb.z) - fmaxf(bx.x, pb.x), 0.0f);
            float ih = fmaxf(fminf(bx.w, pb.w) - fmaxf(bx.y, pb.y), 0.0f);
            float inter = iw * ih;
            float uni   = au.z + w2 * h2 - inter + EPSF;
            float iou   = __fdividef(inter, uni);
            float cw    = fmaxf(bx.z, pb.z) - fminf(bx.x, pb.x);
            float ch    = fmaxf(bx.w, pb.w) - fminf(bx.y, pb.y);
            float c2    = cw * cw + ch * ch + EPSF;
            float dx    = (pb.x + pb.z) - au.x, dy = (pb.y + pb.w) - au.y;
            float rho2  = (dx * dx + dy * dy) * 0.25f;
            float at2   = atanf(__fdividef(w2, h2 + EPSF));
            float da    = at2 - au.w;
            float v     = INV_PI2_4 * da * da;
            float alpha = __fdividef(v, v - iou + (1.0f + EPSF));
            float ciou  = iou - (__fdividef(rho2, c2) + v * alpha);
            bool filt = (g_filt[ba] != 0);
            piou = (filt && (s_val[mg] != 0)) ? fmaxf(ciou, 0.0f) : 0.0f;
        }
        lab        = s_lab[mg];
        r_mg[tid]  = fg ? mg : 0;
        r_m[tid]   = fg ? 1.0f : 0.0f;
    }
    __syncthreads();

    const size_t N  = (size_t)BS * A;
    const size_t bb = (size_t)b * A + blockbase;
    float4* os = (float4*)(out + N * 5 + bb * 80);
    const float4 z4 = make_float4(0.f, 0.f, 0.f, 0.f);

    if (count == TILE) {
        const float m = r_m[tid];
        out[bb + tid]          = (m != 0.0f) ? (float)lab : (float)C;
        out[N * 85 + bb + tid] = m;
        out[N * 86 + bb + tid] = (float)r_mg[tid];
        #pragma unroll
        for (int k = 0; k < 4; k++) {
            int i = k * TILE + tid;
            int al = i >> 2, cp = i & 3;
            out[N + bb * 4 + i] = ((const float*)s_box)[r_mg[al] * 4 + cp] * r_m[al];
        }
        #pragma unroll
        for (int k = 0; k < 20; k++) os[k * TILE + tid] = z4;
        __syncthreads();
        if (r_m[tid] != 0.0f)
            out[N * 5 + (bb + tid) * 80 + lab] = piou;
    } else {
        if (tid < count) {
            const float m = r_m[tid];
            out[bb + tid]          = (m != 0.0f) ? (float)lab : (float)C;
            out[N * 85 + bb + tid] = m;
            out[N * 86 + bb + tid] = (float)r_mg[tid];
        }
        for (int i = tid; i < count * 4; i += TILE) {
            int al = i >> 2, cp = i & 3;
            out[N + bb * 4 + i] = ((const float*)s_box)[r_mg[al] * 4 + cp] * r_m[al];
        }
        for (int i = tid; i < count * 20; i += TILE) os[i] = z4;
        __syncthreads();
        if (tid < count && r_m[tid] != 0.0f)
            out[N * 5 + (bb + tid) * 80 + lab] = piou;
    }
}

// ---------------------------------------------------------------------------
extern "C" void kernel_launch(void* const* d_in, const int* in_sizes, int n_in,
                              void* d_out, int out_size)
{
    const float* scores = (const float*)d_in[0];   // (16, 33600, 80)
    const float* pboxes = (const float*)d_in[1];   // (16, 33600, 4)
    const float* anc    = (const float*)d_in[2];   // (33600, 2)
    const int*   glab   = (const int*)  d_in[3];   // (16, 64, 1)
    const float* gbox   = (const float*)d_in[4];   // (16, 64, 4)
    const int*   gmask  = (const int*)  d_in[5];   // (16, 64, 1)
    const float* strd   = (const float*)d_in[6];   // (16, 33600, 1)
    float* out = (float*)d_out;

    kz<<<1, 1024>>>();
    dim3 gg(NCHUNK, BS);
    k1a<<<gg, TILE>>>(pboxes, anc, gbox, gmask, strd);
    k1b<<<gg, TILE>>>(scores, glab, gbox);
    k2<<<BS * G, 256>>>(scores, pboxes, glab, gbox, gmask);
    k3<<<gg, TILE>>>(pboxes, glab, gbox, gmask, out);
}

// round 13
// speedup vs baseline: 1.8998x; 1.1692x over previous
#include <cuda_runtime.h>
#include <cstdint>

#define BS 16
#define A  33600
#define G  64
#define C  80
#define EPSF 1e-7f
#define CAP 4096

#define TILE 256
#define NCHUNK ((A + TILE - 1) / TILE)

#define INV_PI2_4 0.4052847345693511f

// Scratch (device globals — no runtime allocation allowed)
__device__ unsigned long long g_key[(size_t)BS * G * CAP]; // candidate (fkey(cost)<<32 | a)
__device__ int                g_cnt[BS * G];               // candidate counts
__device__ float              g_iov[(size_t)BS * G * CAP]; // positive iouv values per (b,g)
__device__ int                g_icnt[BS * G];              // value list counts
__device__ float4             g_fpb  [(size_t)BS * A];     // filt anchors: pred box
__device__ int                g_fa   [(size_t)BS * A];     // filt anchors: anchor index
__device__ unsigned long long g_fmask[(size_t)BS * A];     // filt anchors: ic mask
__device__ int                g_fcnt[BS];                  // filt counts
__device__ unsigned char      g_filt[(size_t)BS * A];      // per-anchor anchor_filter
__device__ unsigned long long g_amin[(size_t)BS * A];      // per-anchor argmin (fkey<<6|g)
__device__ int                g_mcnt[(size_t)BS * A];      // match count per anchor
__device__ int                g_mfg [(size_t)BS * A];      // min matched g per anchor

// Monotone float -> uint32 order-preserving transform
__device__ __forceinline__ unsigned int fkey(float f) {
    unsigned int b = __float_as_uint(f);
    return b ^ ((unsigned int)((int)b >> 31) | 0x80000000u);
}

// ---------------------------------------------------------------------------
// KZ: zero small counters (single block)
// ---------------------------------------------------------------------------
__global__ void kz() {
    int i = threadIdx.x;
    if (i < BS * G) { g_cnt[i] = 0; g_icnt[i] = 0; }
    if (i < BS)     g_fcnt[i] = 0;
}

// ---------------------------------------------------------------------------
// K1a: per (b,a): in-center mask + compaction of filt anchors into per-batch
// lists; also zero-inits per-anchor match state.
// ---------------------------------------------------------------------------
__global__ __launch_bounds__(TILE) void k1a(
    const float* __restrict__ pboxes, const float* __restrict__ anc,
    const float* __restrict__ gbox,   const int*   __restrict__ gmask,
    const float* __restrict__ strd)
{
    __shared__ float2 s_gc[G];
    __shared__ unsigned int s_vm[2];

    const int tid = threadIdx.x;
    const int b   = blockIdx.y;

    if (tid < G) {
        const float* gb = gbox + ((size_t)b * G + tid) * 4;
        s_gc[tid] = make_float2((gb[0] + gb[2]) * 0.5f, (gb[1] + gb[3]) * 0.5f);
        unsigned int bal = __ballot_sync(0xFFFFFFFFu, gmask[b * G + tid] != 0);
        if ((tid & 31) == 0) s_vm[tid >> 5] = bal;
    }
    __syncthreads();

    const int a = blockIdx.x * TILE + tid;
    if (a >= A) return;   // warp-uniform (A % 32 == 0)

    const size_t ba = (size_t)b * A + a;
    g_mcnt[ba] = 0;
    g_mfg [ba] = 0x7FFFFFFF;
    g_amin[ba] = 0xFFFFFFFFFFFFFFFFull;

    const unsigned long long vmask =
        (unsigned long long)s_vm[0] | ((unsigned long long)s_vm[1] << 32);

    const float ax = anc[a * 2 + 0], ay = anc[a * 2 + 1];
    const float cd = strd[ba] * 2.5f;

    unsigned long long mask = 0ull;
    #pragma unroll
    for (int g = 0; g < G; g++) {
        float2 gc = s_gc[g];
        bool ic = (fabsf(ax - gc.x) < cd) && (fabsf(ay - gc.y) < cd);
        mask |= ((unsigned long long)ic) << g;
    }
    mask &= vmask;
    const bool filt = (mask != 0ull);
    g_filt[ba] = filt ? 1 : 0;

    unsigned int fm = __ballot_sync(0xFFFFFFFFu, filt);
    if (filt) {
        const float4 pb = *(const float4*)(pboxes + ba * 4);
        int lane   = tid & 31;
        int leader = __ffs(fm) - 1;
        int basei = 0;
        if (lane == leader) basei = atomicAdd(&g_fcnt[b], __popc(fm));
        basei = __shfl_sync(fm, basei, leader);
        int slot = basei + __popc(fm & ((1u << lane) - 1u));
        size_t off = (size_t)b * A + slot;
        g_fpb  [off] = pb;
        g_fa   [off] = a;
        g_fmask[off] = mask;
    }
}

// ---------------------------------------------------------------------------
// K1b: dense pass over the compacted filt-anchor list.
// Branch-free intersect|ic bitmask, then while over SET BITS only
// (warp-max ~12-16 iters). One CIoU per set bit; positive iouv -> per-(b,g)
// value list (zeros can't affect top-10); ic bits emit cost key + argmin.
// ---------------------------------------------------------------------------
__global__ __launch_bounds__(TILE) void k1b(
    const float* __restrict__ scores, const int* __restrict__ glab,
    const float* __restrict__ gbox,   const int* __restrict__ gmask)
{
    __shared__ float4 s_box[G];
    __shared__ float4 s_aux[G];   // sx, sy, w1h1, at1
    __shared__ int    s_lab[G];
    __shared__ unsigned int s_vm[2];

    const int tid = threadIdx.x;
    const int b   = blockIdx.y;

    if (tid < G) {
        const float* gb = gbox + ((size_t)b * G + tid) * 4;
        float x1 = gb[0], y1 = gb[1], x2 = gb[2], y2 = gb[3];
        s_box[tid] = make_float4(x1, y1, x2, y2);
        float w1 = x2 - x1, h1 = y2 - y1;
        s_aux[tid] = make_float4(x1 + x2, y1 + y2, w1 * h1, atanf(__fdividef(w1, h1 + EPSF)));
        s_lab[tid] = glab[b * G + tid];
        unsigned int bal = __ballot_sync(0xFFFFFFFFu, gmask[b * G + tid] != 0);
        if ((tid & 31) == 0) s_vm[tid >> 5] = bal;
    }
    __syncthreads();

    const int i = blockIdx.x * TILE + tid;
    if (i >= g_fcnt[b]) return;

    const unsigned long long vmask =
        (unsigned long long)s_vm[0] | ((unsigned long long)s_vm[1] << 32);

    const size_t off = (size_t)b * A + i;
    const int a = g_fa[off];
    const float4 pb = g_fpb[off];
    const float w2 = pb.z - pb.x, h2 = pb.w - pb.y;
    const float w2h2 = w2 * h2;
    const float at2  = atanf(__fdividef(w2, h2 + EPSF));
    const unsigned long long mask = g_fmask[off];   // ic & vmask
    const float psx = pb.x + pb.z, psy = pb.y + pb.w;

    const size_t ba = (size_t)b * A + a;
    const float* srow = scores + ba * C;

    // base = sum_c -log1p(-sqrt(s_c))
    float base = 0.0f;
    const float4* srow4 = (const float4*)srow;
    #pragma unroll
    for (int q = 0; q < C / 4; q++) {
        float4 v = srow4[q];
        float ss[4] = {v.x, v.y, v.z, v.w};
        #pragma unroll
        for (int j = 0; j < 4; j++) {
            float p = __fsqrt_rn(ss[j]);
            base -= fmaxf(__logf(1.0f - p), -100.0f);
        }
    }

    // Branch-free intersect mask
    unsigned long long im = 0ull;
    #pragma unroll 8
    for (int g = 0; g < G; g++) {
        const float4 bx = s_box[g];
        bool ix = (fminf(bx.z, pb.z) > fmaxf(bx.x, pb.x)) &&
                  (fminf(bx.w, pb.w) > fmaxf(bx.y, pb.y));
        im |= ((unsigned long long)ix) << g;
    }
    im = (im & vmask) | mask;

    unsigned long long amin = 0xFFFFFFFFFFFFFFFFull;
    unsigned long long mm = im;
    while (mm) {
        int g = __ffsll((long long)mm) - 1;
        mm &= mm - 1;
        const float4 bx = s_box[g];
        const float4 au = s_aux[g];
        float iw = fmaxf(fminf(bx.z, pb.z) - fmaxf(bx.x, pb.x), 0.0f);
        float ih = fmaxf(fminf(bx.w, pb.w) - fmaxf(bx.y, pb.y), 0.0f);
        float inter = iw * ih;
        float uni   = au.z + w2h2 - inter + EPSF;
        float iou   = __fdividef(inter, uni);
        float cw    = fmaxf(bx.z, pb.z) - fminf(bx.x, pb.x);
        float ch    = fmaxf(bx.w, pb.w) - fminf(bx.y, pb.y);
        float c2    = cw * cw + ch * ch + EPSF;
        float dx    = psx - au.x, dy = psy - au.y;
        float rho2  = (dx * dx + dy * dy) * 0.25f;
        float da    = at2 - au.w;
        float v     = INV_PI2_4 * da * da;
        float alpha = __fdividef(v, v - iou + (1.0f + EPSF));
        float ciou  = iou - (__fdividef(rho2, c2) + v * alpha);
        float iouv  = fmaxf(ciou, 0.0f);

        if (iouv > 0.0f) {
            int slot = atomicAdd(&g_icnt[b * G + g], 1);
            if (slot < CAP) g_iov[(size_t)(b * G + g) * CAP + slot] = iouv;
        }

        if ((mask >> g) & 1ull) {
            float s   = srow[s_lab[g]];
            float p   = __fsqrt_rn(s);
            float lp  = fmaxf(0.5f * __logf(s), -100.0f);
            float l1m = fmaxf(__logf(1.0f - p), -100.0f);
            float cost = base + (l1m - lp) - 3.0f * __logf(iouv + 1e-8f);

            unsigned int k32 = fkey(cost);
            unsigned long long pk = (((unsigned long long)k32) << 6) | (unsigned int)g;
            if (pk < amin) amin = pk;

            int slot = atomicAdd(&g_cnt[b * G + g], 1);
            if (slot < CAP)
                g_key[(size_t)(b * G + g) * CAP + slot] =
                    (((unsigned long long)k32) << 32) | (unsigned int)a;
        }
    }
    g_amin[ba] = amin;
}

// ---------------------------------------------------------------------------
// K2: block per (b,g). Phase A: scan tiny per-gt value list -> per-thread
// top-10 -> parallel merge tree -> dyn_k. Phase B (warp 0): threshold + mark.
// ---------------------------------------------------------------------------
__global__ __launch_bounds__(256, 6) void k2(
    const float* __restrict__ scores, const float* __restrict__ pboxes,
    const int* __restrict__ glab, const float* __restrict__ gbox,
    const int* __restrict__ gmask)
{
    __shared__ float fc[10 * 256];
    __shared__ int   s_dynk;

    const int bg  = blockIdx.x;
    const int tid = threadIdx.x;
    const int b = bg >> 6, g = bg & 63;
    if (gmask[bg] == 0) return;

    const int n_i = min(g_icnt[bg], CAP);
    const float* vl = g_iov + (size_t)bg * CAP;
    float top[10];
    #pragma unroll
    for (int j = 0; j < 10; j++) top[j] = 0.0f;
    for (int i = tid; i < n_i; i += 256) {
        float v = vl[i];
        if (v > top[9]) {
            top[9] = v;
            #pragma unroll
            for (int j = 8; j >= 0; j--)
                if (top[j + 1] > top[j]) { float t = top[j]; top[j] = top[j + 1]; top[j + 1] = t; }
        }
    }
    #pragma unroll
    for (int j = 0; j < 10; j++) fc[j * 256 + tid] = top[j];
    __syncthreads();

    for (int s = 128; s >= 1; s >>= 1) {
        if (tid < s) {
            #pragma unroll
            for (int j = 0; j < 10; j++) {
                float v = fc[j * 256 + tid + s];
                if (v > top[9]) {
                    top[9] = v;
                    #pragma unroll
                    for (int t = 8; t >= 0; t--)
                        if (top[t + 1] > top[t]) { float tt = top[t]; top[t] = top[t + 1]; top[t + 1] = tt; }
                }
            }
            #pragma unroll
            for (int j = 0; j < 10; j++) fc[j * 256 + tid] = top[j];
        }
        __syncthreads();
    }
    if (tid == 0) {
        float sum = 0.0f;
        #pragma unroll
        for (int j = 0; j < 10; j++) sum += top[j];   // descending = top_k sum order
        s_dynk = max((int)(sum + 0.5f), 1);
    }
    __syncthreads();
    const int dynk = s_dynk;

    if (tid >= 32) return;
    const int lane = tid;

    const int n = min(g_cnt[bg], CAP);
    const unsigned long long* kl = g_key + (size_t)bg * CAP;

    if (n > 0) {
        unsigned long long bot[10];
        #pragma unroll
        for (int j = 0; j < 10; j++) bot[j] = 0xFFFFFFFFFFFFFFFFull;
        for (int i = lane; i < n; i += 32) {
            unsigned long long key = kl[i];
            if (key < bot[9]) {
                bot[9] = key;
                #pragma unroll
                for (int j = 8; j >= 0; j--)
                    if (bot[j + 1] < bot[j]) { unsigned long long t = bot[j]; bot[j] = bot[j + 1]; bot[j + 1] = t; }
            }
        }
        unsigned long long T = 0xFFFFFFFFFFFFFFFFull;
        for (int r = 0; r < dynk; r++) {
            unsigned long long m = bot[0];
            #pragma unroll
            for (int o = 16; o > 0; o >>= 1) {
                unsigned long long om = __shfl_xor_sync(0xFFFFFFFFu, m, o);
                if (om < m) m = om;
            }
            T = m;
            if (bot[0] == m) {                   // keys unique; static shift-down
                #pragma unroll
                for (int t = 0; t < 9; t++) bot[t] = bot[t + 1];
                bot[9] = 0xFFFFFFFFFFFFFFFFull;
            }
        }
        for (int i = lane; i < n; i += 32) {
            unsigned long long key = kl[i];
            if (key <= T) {
                unsigned int aa = (unsigned int)key;
                atomicAdd(&g_mcnt[(size_t)b * A + aa], 1);
                atomicMin(&g_mfg [(size_t)b * A + aa], g);
            }
        }
    } else {
        // Fallback (statistically unreachable): warp-level global row min.
        const float* gb = gbox + (size_t)bg * 4;
        const float x1 = gb[0], y1 = gb[1], x2 = gb[2], y2 = gb[3];
        const float w1 = x2 - x1, h1 = y2 - y1, w1h1 = w1 * h1;
        const float at1 = atanf(__fdividef(w1, h1 + EPSF));
        const float sx = x1 + x2, sy = y1 + y2;
        const int lab = glab[bg];
        unsigned long long best = 0xFFFFFFFFFFFFFFFFull;
        for (int a = lane; a < A; a += 32) {
            const size_t ba = (size_t)b * A + a;
            float4 pb = *(const float4*)(pboxes + ba * 4);
            float w2 = pb.z - pb.x, h2 = pb.w - pb.y;
            float iw = fmaxf(fminf(x2, pb.z) - fmaxf(x1, pb.x), 0.0f);
            float ih = fmaxf(fminf(y2, pb.w) - fmaxf(y1, pb.y), 0.0f);
            float inter = iw * ih;
            float uni   = w1h1 + w2 * h2 - inter + EPSF;
            float iou   = __fdividef(inter, uni);
            float cw    = fmaxf(x2, pb.z) - fminf(x1, pb.x);
            float ch    = fmaxf(y2, pb.w) - fminf(y1, pb.y);
            float c2    = cw * cw + ch * ch + EPSF;
            float dx    = (pb.x + pb.z) - sx, dy = (pb.y + pb.w) - sy;
            float rho2  = (dx * dx + dy * dy) * 0.25f;
            float at2   = atanf(__fdividef(w2, h2 + EPSF));
            float da    = at2 - at1;
            float v     = INV_PI2_4 * da * da;
            float alpha = __fdividef(v, v - iou + (1.0f + EPSF));
            float ciou  = iou - (__fdividef(rho2, c2) + v * alpha);

            bool filt = g_filt[ba] != 0;
            float iouv = filt ? fmaxf(ciou, 0.0f) : 0.0f;

            float base = 0.0f;
            const float4* s4 = (const float4*)(scores + ba * C);
            #pragma unroll 4
            for (int qq = 0; qq < C / 4; qq++) {
                float4 vv = s4[qq];
                base -= fmaxf(__logf(1.0f - __fsqrt_rn(vv.x)), -100.0f);
                base -= fmaxf(__logf(1.0f - __fsqrt_rn(vv.y)), -100.0f);
                base -= fmaxf(__logf(1.0f - __fsqrt_rn(vv.z)), -100.0f);
                base -= fmaxf(__logf(1.0f - __fsqrt_rn(vv.w)), -100.0f);
            }
            float s = scores[ba * C + lab];
            float pp = __fsqrt_rn(s);
            float lp  = fmaxf(0.5f * __logf(s), -100.0f);
            float l1m = fmaxf(__logf(1.0f - pp), -100.0f);
            float cost = base + (l1m - lp) - 3.0f * __logf(iouv + 1e-8f)
                       + 1e6f + (filt ? 0.0f : 1e8f);
            unsigned long long key = (((unsigned long long)fkey(cost)) << 32) | (unsigned int)a;
            if (key < best) best = key;
        }
        #pragma unroll
        for (int o = 16; o > 0; o >>= 1) {
            unsigned long long om = __shfl_xor_sync(0xFFFFFFFFu, best, o);
            if (om < best) best = om;
        }
        if (lane == 0) {
            unsigned int aa = (unsigned int)best;
            atomicAdd(&g_mcnt[(size_t)b * A + aa], 1);
            atomicMin(&g_mfg [(size_t)b * A + aa], g);
            atomicMin(&g_amin[(size_t)b * A + aa],
                      ((best >> 32) << 6) | (unsigned long long)g);
        }
    }
}

// ---------------------------------------------------------------------------
// K3: per anchor: resolve matches, recompute pred_iou, coalesced outputs.
// Output layout (tuple order): labels | tboxes | tscores | fg | tgt_idx
// ---------------------------------------------------------------------------
__global__ __launch_bounds__(TILE) void k3(
    const float* __restrict__ pboxes, const int* __restrict__ glab,
    const float* __restrict__ gbox,   const int* __restrict__ gmask,
    float* __restrict__ out)
{
    __shared__ float4 s_box[G];
    __shared__ float4 s_aux[G];   // sx, sy, w1h1, at1
    __shared__ int    s_lab[G], s_val[G];
    __shared__ int    r_mg[TILE];
    __shared__ float  r_m [TILE];

    const int tid = threadIdx.x;
    const int b   = blockIdx.y;
    if (tid < G) {
        const float* gb = gbox + ((size_t)b * G + tid) * 4;
        float x1 = gb[0], y1 = gb[1], x2 = gb[2], y2 = gb[3];
        s_box[tid] = make_float4(x1, y1, x2, y2);
        float w1 = x2 - x1, h1 = y2 - y1;
        s_aux[tid] = make_float4(x1 + x2, y1 + y2, w1 * h1, atanf(__fdividef(w1, h1 + EPSF)));
        s_lab[tid] = glab[b * G + tid];
        s_val[tid] = gmask[b * G + tid];
    }
    __syncthreads();

    const int blockbase = blockIdx.x * TILE;
    const int count = min(TILE, A - blockbase);
    const int a = blockbase + tid;

    float piou = 0.0f;
    int   lab  = 0;
    if (tid < count) {
        const size_t ba = (size_t)b * A + a;
        const int cnt = g_mcnt[ba];
        const bool fg = (cnt > 0);
        int mg = 0;
        if (fg) {
            mg = (cnt > 1) ? (int)(g_amin[ba] & 63ull) : g_mfg[ba];
            float4 pb = *(const float4*)(pboxes + ba * 4);
            float4 bx = s_box[mg];
            float4 au = s_aux[mg];
            float w2 = pb.z - pb.x, h2 = pb.w - pb.y;
            float iw = fmaxf(fminf(bx.z, pb.z) - fmaxf(bx.x, pb.x), 0.0f);
            float ih = fmaxf(fminf(bx.w, pb.w) - fmaxf(bx.y, pb.y), 0.0f);
            float inter = iw * ih;
            float uni   = au.z + w2 * h2 - inter + EPSF;
            float iou   = __fdividef(inter, uni);
            float cw    = fmaxf(bx.z, pb.z) - fminf(bx.x, pb.x);
            float ch    = fmaxf(bx.w, pb.w) - fminf(bx.y, pb.y);
            float c2    = cw * cw + ch * ch + EPSF;
            float dx    = (pb.x + pb.z) - au.x, dy = (pb.y + pb.w) - au.y;
            float rho2  = (dx * dx + dy * dy) * 0.25f;
            float at2   = atanf(__fdividef(w2, h2 + EPSF));
            float da    = at2 - au.w;
            float v     = INV_PI2_4 * da * da;
            float alpha = __fdividef(v, v - iou + (1.0f + EPSF));
            float ciou  = iou - (__fdividef(rho2, c2) + v * alpha);
            bool filt = (g_filt[ba] != 0);
            piou = (filt && (s_val[mg] != 0)) ? fmaxf(ciou, 0.0f) : 0.0f;
        }
        lab        = s_lab[mg];
        r_mg[tid]  = fg ? mg : 0;
        r_m[tid]   = fg ? 1.0f : 0.0f;
    }
    __syncthreads();

    const size_t N  = (size_t)BS * A;
    const size_t bb = (size_t)b * A + blockbase;
    float4* os = (float4*)(out + N * 5 + bb * 80);
    const float4 z4 = make_float4(0.f, 0.f, 0.f, 0.f);

    if (count == TILE) {
        const float m = r_m[tid];
        out[bb + tid]          = (m != 0.0f) ? (float)lab : (float)C;
        out[N * 85 + bb + tid] = m;
        out[N * 86 + bb + tid] = (float)r_mg[tid];
        #pragma unroll
        for (int k = 0; k < 4; k++) {
            int i = k * TILE + tid;
            int al = i >> 2, cp = i & 3;
            out[N + bb * 4 + i] = ((const float*)s_box)[r_mg[al] * 4 + cp] * r_m[al];
        }
        #pragma unroll
        for (int k = 0; k < 20; k++) os[k * TILE + tid] = z4;
        __syncthreads();
        if (r_m[tid] != 0.0f)
            out[N * 5 + (bb + tid) * 80 + lab] = piou;
    } else {
        if (tid < count) {
            const float m = r_m[tid];
            out[bb + tid]          = (m != 0.0f) ? (float)lab : (float)C;
            out[N * 85 + bb + tid] = m;
            out[N * 86 + bb + tid] = (float)r_mg[tid];
        }
        for (int i = tid; i < count * 4; i += TILE) {
            int al = i >> 2, cp = i & 3;
            out[N + bb * 4 + i] = ((const float*)s_box)[r_mg[al] * 4 + cp] * r_m[al];
        }
        for (int i = tid; i < count * 20; i += TILE) os[i] = z4;
        __syncthreads();
        if (tid < count && r_m[tid] != 0.0f)
            out[N * 5 + (bb + tid) * 80 + lab] = piou;
    }
}

// ---------------------------------------------------------------------------
extern "C" void kernel_launch(void* const* d_in, const int* in_sizes, int n_in,
                              void* d_out, int out_size)
{
    const float* scores = (const float*)d_in[0];   // (16, 33600, 80)
    const float* pboxes = (const float*)d_in[1];   // (16, 33600, 4)
    const float* anc    = (const float*)d_in[2];   // (33600, 2)
    const int*   glab   = (const int*)  d_in[3];   // (16, 64, 1)
    const float* gbox   = (const float*)d_in[4];   // (16, 64, 4)
    const int*   gmask  = (const int*)  d_in[5];   // (16, 64, 1)
    const float* strd   = (const float*)d_in[6];   // (16, 33600, 1)
    float* out = (float*)d_out;

    kz<<<1, 1024>>>();
    dim3 gg(NCHUNK, BS);
    k1a<<<gg, TILE>>>(pboxes, anc, gbox, gmask, strd);
    k1b<<<gg, TILE>>>(scores, glab, gbox, gmask);
    k2<<<BS * G, 256>>>(scores, pboxes, glab, gbox, gmask);
    k3<<<gg, TILE>>>(pboxes, glab, gbox, gmask, out);
}